// round 10
// baseline (speedup 1.0000x reference)
#include <cuda_runtime.h>
#include <math.h>

// ---------------- problem constants ----------------
#define NBATCH 1024
#define NP     31
#define RHD    128
#define NC     11

typedef unsigned long long ull;

// ---------------- f32x2 packed-FMA helpers ----------------
__device__ __forceinline__ void ffma2(ull& d, ull a, ull b) {
    asm("fma.rn.f32x2 %0, %1, %2, %0;" : "+l"(d) : "l"(a), "l"(b));
}
__device__ __forceinline__ float2 unpack2(ull v) {
    float2 r; asm("mov.b64 {%0,%1}, %2;" : "=f"(r.x), "=f"(r.y) : "l"(v)); return r;
}
__device__ __forceinline__ float sigm(float x) { return 1.0f / (1.0f + expf(-x)); }

// ---------------- device scratch ----------------
__device__ float g_awT[17 * 64];          // [k][i] banded adj * deg_inv (scalar)
__device__ float g_awT2[17 * 64 * 2];     // [k][i] duplicated pairs (ull view)
__device__ float g_b1[64];
__device__ float g_b2[64];
__device__ float g_w1[256];               // [Ws1t(2x64) ; Wn1t(2x64)]
__device__ float g_Ws2p[4096];            // packed: [dp][o*2+par], par = d&1
__device__ float g_Wn2p[4096];
__device__ float g_b0c[512];
__device__ float g_b1l[512];
__device__ float g_Wih0t[64 * 512];       // [k][n]
__device__ float g_Wc1t[128 * 64];        // [k][o]
__device__ float g_feats[NBATCH * NP * 64];
__device__ float g_xg0[NBATCH * NP * 512];
__device__ float g_H0[2][NBATCH * RHD];
__device__ float g_C0[NBATCH * RHD];
__device__ float g_H1[2][NBATCH * RHD];
__device__ float g_C1[NBATCH * RHD];
__device__ float g_hid[NBATCH * 64];

// ---------------- prep (small, single block) ----------------
__global__ void prep_kernel(const float* __restrict__ E,
                            const float* __restrict__ Wn1, const float* __restrict__ bn1,
                            const float* __restrict__ Ws1, const float* __restrict__ bs1,
                            const float* __restrict__ Wn2, const float* __restrict__ bn2,
                            const float* __restrict__ Ws2, const float* __restrict__ bs2,
                            const float* __restrict__ bih0, const float* __restrict__ bhh0,
                            const float* __restrict__ bih1, const float* __restrict__ bhh1) {
    const int tid = threadIdx.x;
    if (tid < 64) {
        float row[17];
        float deg = 0.0f;
#pragma unroll
        for (int k = 0; k < 17; k++) {
            int j = tid - 8 + k;
            float a = 0.0f;
            if (j >= 0 && j < 64 && j != tid) a = 1.0f / (1.0f + expf(-E[tid * 64 + j]));
            row[k] = a;
            deg += a;
        }
        float inv = deg > 0.0f ? 1.0f / deg : 0.0f;
#pragma unroll
        for (int k = 0; k < 17; k++) g_awT[k * 64 + tid] = row[k] * inv;
        g_b1[tid] = bs1[tid] + bn1[tid];
        g_b2[tid] = bs2[tid] + bn2[tid];
        g_w1[tid]       = Ws1[tid * 2 + 0];
        g_w1[64 + tid]  = Ws1[tid * 2 + 1];
        g_w1[128 + tid] = Wn1[tid * 2 + 0];
        g_w1[192 + tid] = Wn1[tid * 2 + 1];
    }
    __syncthreads();
    for (int idx = tid; idx < 17 * 64; idx += 256) {
        float v = g_awT[idx];
        g_awT2[idx * 2 + 0] = v;
        g_awT2[idx * 2 + 1] = v;
    }
    // packed SAGE2 weights: g_*p[dp*128 + o*2 + par] = W[o][2dp+par]
    for (int idx = tid; idx < 4096; idx += 256) {
        int dp = idx >> 7, rem = idx & 127;
        int o = rem >> 1, par = rem & 1;
        g_Ws2p[idx] = Ws2[o * 64 + 2 * dp + par];
        g_Wn2p[idx] = Wn2[o * 64 + 2 * dp + par];
    }
    for (int idx = tid; idx < 512; idx += 256) {
        g_b0c[idx] = bih0[idx] + bhh0[idx];
        g_b1l[idx] = bih1[idx] + bhh1[idx];
    }
}

// ---------------- prep (big transposes, multi-block) ----------------
__global__ void prep_big_kernel(const float* __restrict__ Wih0,
                                const float* __restrict__ Wc1) {
    int idx = blockIdx.x * blockDim.x + threadIdx.x;
    if (idx < 512 * 64) {
        int n = idx >> 6, k = idx & 63;
        g_Wih0t[k * 512 + n] = Wih0[idx];
    }
    if (idx < 64 * 128) {
        int o = idx >> 7, k = idx & 127;
        g_Wc1t[k * 64 + o] = Wc1[idx];
    }
}

__global__ void zero_kernel() {
    int i = blockIdx.x * blockDim.x + threadIdx.x;
    if (i < NBATCH * RHD) {
        g_H0[1][i] = 0.0f;
        g_C0[i]    = 0.0f;
        g_H1[1][i] = 0.0f;
        g_C1[i]    = 0.0f;
    }
}

// ---------------- fused GNN: 2 patches per CTA, joint GEMM ----------------
// smem layout (float offsets):
//   x1a @0      [4096]
//   n1a @4096   [4096]
//   x1b @8192   [4096]
//   n1b @12288  [4096]
//   Wsp @16384  [4096]
//   Wnp @20480  [4096]
//   awT2@24576  [2176]
//   x0  @26752  [128]
//   n0  @26880  [128]
//   w1  @27008  [256]
//   b1s @27264  [64]
//   b2s @27328  [64]
//   total 27392 floats = 109568 bytes  (2 CTAs/SM: 219136 B <= 228KB carveout)
#define GNN_SMEM_FLOATS 27392
__global__ __launch_bounds__(256, 2) void gnn_kernel(const float* __restrict__ I,
                                                     const float* __restrict__ Q) {
    extern __shared__ float sm[];
    float* const x1a  = sm;
    float* const n1a  = sm + 4096;
    float* const x1b  = sm + 8192;
    float* const n1b  = sm + 12288;
    float* const Wsp  = sm + 16384;
    float* const Wnp  = sm + 20480;
    float* const awT2 = sm + 24576;
    float* const x0   = sm + 26752;
    float* const n0   = sm + 26880;
    float* const w1   = sm + 27008;
    float* const b1s  = sm + 27264;
    float* const b2s  = sm + 27328;

    const int tid = threadIdx.x;

    for (int idx = tid; idx < 1024; idx += 256) {
        ((float4*)Wsp)[idx] = ((const float4*)g_Ws2p)[idx];
        ((float4*)Wnp)[idx] = ((const float4*)g_Wn2p)[idx];
    }
    for (int idx = tid; idx < 2176; idx += 256) awT2[idx] = g_awT2[idx];
    w1[tid] = g_w1[tid];
    if (tid < 64) {
        b1s[tid] = g_b1[tid];
        b2s[tid] = g_b2[tid];
    }

    const int gp0 = blockIdx.x * 2;

    // ---- per-patch phases: x0 -> neigh0 -> sage1 -> conv ----
#pragma unroll 1
    for (int pp = 0; pp < 2; pp++) {
        const int gp = gp0 + pp;
        const int b  = gp / NP;
        const int p  = gp - b * NP;
        float* x1 = pp ? x1b : x1a;
        float* n1 = pp ? n1b : n1a;
        __syncthreads();
        if (tid < 64) {
            int pos = b * 1024 + p * 32 + tid;
            x0[tid * 2 + 0] = I[pos];
            x0[tid * 2 + 1] = Q[pos];
        }
        __syncthreads();

        // neigh0[i][dd] (dd=2)
        if (tid < 128) {
            int i = tid >> 1, dd = tid & 1;
            float s = 0.0f;
#pragma unroll
            for (int k = 0; k < 17; k++) {
                int j = i - 8 + k;
                j = max(0, min(63, j));
                s += awT2[(k * 64 + i) * 2] * x0[j * 2 + dd];
            }
            n0[tid] = s;
        }
        __syncthreads();

        // SAGE layer 1
        {
            const int o = tid & 63, ig = tid >> 6;
            const float ws0 = w1[o], ws1 = w1[64 + o], wn0 = w1[128 + o], wn1 = w1[192 + o];
            const float bb = b1s[o];
#pragma unroll
            for (int ii = 0; ii < 16; ii++) {
                int i = ig * 16 + ii;
                float v = bb + x0[i * 2] * ws0 + x0[i * 2 + 1] * ws1
                             + n0[i * 2] * wn0 + n0[i * 2 + 1] * wn1;
                x1[i * 64 + o] = fmaxf(v, 0.0f);
            }
        }
        __syncthreads();

        // banded conv -> n1: f32x2 over d-pairs with sliding register window over i
        {
            const int dp = tid & 31;
            const int ig = tid >> 5;     // 0..7
            const int i0 = ig * 8;
            ull xw[24];
#pragma unroll
            for (int w = 0; w < 24; w++) {
                int j = i0 - 8 + w;
                j = max(0, min(63, j));
                xw[w] = *(const ull*)(x1 + j * 64 + 2 * dp);
            }
            ull acc[8];
#pragma unroll
            for (int ii = 0; ii < 8; ii++) acc[ii] = 0ull;
#pragma unroll
            for (int k = 0; k < 17; k++) {
#pragma unroll
                for (int ii = 0; ii < 8; ii += 2) {
                    const ulonglong2 aw = *(const ulonglong2*)(awT2 + (k * 64 + i0 + ii) * 2);
                    ffma2(acc[ii],     aw.x, xw[ii + k]);
                    ffma2(acc[ii + 1], aw.y, xw[ii + 1 + k]);
                }
            }
#pragma unroll
            for (int ii = 0; ii < 8; ii++)
                *(ull*)(n1 + (i0 + ii) * 64 + 2 * dp) = acc[ii];
        }
    }
    __syncthreads();

    // ---- joint SAGE2 GEMM over both patches (shared weight loads) ----
    {
        const int ol = tid & 15;            // o = ol + 16c
        const int ig = tid >> 4;            // 0..15
        const int i0 = ig * 4;
        ull accA[4][4], accB[4][4];
#pragma unroll
        for (int ii = 0; ii < 4; ii++)
#pragma unroll
            for (int c = 0; c < 4; c++) { accA[ii][c] = 0ull; accB[ii][c] = 0ull; }

#pragma unroll 1
        for (int dp = 0; dp < 32; dp += 2) {
#pragma unroll
            for (int h = 0; h < 2; h++) {
                ull ws0[2], wn0[2], ws1[2], wn1[2];
#pragma unroll
                for (int cc = 0; cc < 2; cc++) {
                    const int oo = (ol + 16 * (2 * h + cc)) * 2;
                    ws0[cc] = *(const ull*)(Wsp + dp * 128 + oo);
                    wn0[cc] = *(const ull*)(Wnp + dp * 128 + oo);
                    ws1[cc] = *(const ull*)(Wsp + (dp + 1) * 128 + oo);
                    wn1[cc] = *(const ull*)(Wnp + (dp + 1) * 128 + oo);
                }
#pragma unroll
                for (int ii = 0; ii < 4; ii++) {
                    const ulonglong2 aA = *(const ulonglong2*)(x1a + (i0 + ii) * 64 + 2 * dp);
                    const ulonglong2 eA = *(const ulonglong2*)(n1a + (i0 + ii) * 64 + 2 * dp);
#pragma unroll
                    for (int cc = 0; cc < 2; cc++) {
                        ffma2(accA[ii][2 * h + cc], aA.x, ws0[cc]);
                        ffma2(accA[ii][2 * h + cc], eA.x, wn0[cc]);
                        ffma2(accA[ii][2 * h + cc], aA.y, ws1[cc]);
                        ffma2(accA[ii][2 * h + cc], eA.y, wn1[cc]);
                    }
                    const ulonglong2 aB = *(const ulonglong2*)(x1b + (i0 + ii) * 64 + 2 * dp);
                    const ulonglong2 eB = *(const ulonglong2*)(n1b + (i0 + ii) * 64 + 2 * dp);
#pragma unroll
                    for (int cc = 0; cc < 2; cc++) {
                        ffma2(accB[ii][2 * h + cc], aB.x, ws0[cc]);
                        ffma2(accB[ii][2 * h + cc], eB.x, wn0[cc]);
                        ffma2(accB[ii][2 * h + cc], aB.y, ws1[cc]);
                        ffma2(accB[ii][2 * h + cc], eB.y, wn1[cc]);
                    }
                }
            }
        }

        float fsA[4], fsB[4];
#pragma unroll
        for (int c = 0; c < 4; c++) {
            const float bb = b2s[ol + 16 * c];
            float sA = 0.0f, sB = 0.0f;
#pragma unroll
            for (int ii = 0; ii < 4; ii++) {
                float2 vA = unpack2(accA[ii][c]);
                float2 vB = unpack2(accB[ii][c]);
                sA += fmaxf(vA.x + vA.y + bb, 0.0f);
                sB += fmaxf(vB.x + vB.y + bb, 0.0f);
            }
            fsA[c] = sA; fsB[c] = sB;
        }
        __syncthreads();   // done reading x1a/x1b — reuse as reduction buffers
#pragma unroll
        for (int c = 0; c < 4; c++) {
            x1a[ig * 64 + ol + 16 * c] = fsA[c];
            x1b[ig * 64 + ol + 16 * c] = fsB[c];
        }
    }
    __syncthreads();
    if (tid < 64) {
        float s = 0.0f;
#pragma unroll
        for (int g = 0; g < 16; g++) s += x1a[g * 64 + tid];
        g_feats[gp0 * 64 + tid] = s;
    } else if (tid < 128) {
        const int o = tid - 64;
        float s = 0.0f;
#pragma unroll
        for (int g = 0; g < 16; g++) s += x1b[g * 64 + o];
        g_feats[(gp0 + 1) * 64 + o] = s;
    }
}

// ---------------- xg0 = feats @ Wih0^T + bias : [31744 x 512], K=64 ----------------
__global__ __launch_bounds__(256) void xg0_kernel() {
    __shared__ float As[64 * 64];
    __shared__ float Bs[64 * 64];
    __shared__ float bsm[64];
    const int m0 = blockIdx.x * 64;
    const int n0 = blockIdx.y * 64;
    const int tid = threadIdx.x;
    for (int idx = tid; idx < 1024; idx += 256)
        ((float4*)As)[idx] = *(const float4*)(g_feats + (m0 + (idx >> 4)) * 64 + (idx & 15) * 4);
    for (int idx = tid; idx < 1024; idx += 256)
        ((float4*)Bs)[idx] = *(const float4*)(g_Wih0t + (idx >> 4) * 512 + n0 + (idx & 15) * 4);
    if (tid < 64) bsm[tid] = g_b0c[n0 + tid];
    __syncthreads();
    const int mi0 = (tid >> 4) * 4;
    const int ni0 = (tid & 15) * 4;
    ull acc[4][2];
#pragma unroll
    for (int ii = 0; ii < 4; ii++) { acc[ii][0] = 0ull; acc[ii][1] = 0ull; }
#pragma unroll 2
    for (int k = 0; k < 64; k += 4) {
        ulonglong2 bv[4];
#pragma unroll
        for (int kk = 0; kk < 4; kk++) bv[kk] = *(const ulonglong2*)(Bs + (k + kk) * 64 + ni0);
#pragma unroll
        for (int ii = 0; ii < 4; ii++) {
            const float4 a = *(const float4*)(As + (mi0 + ii) * 64 + k);
            ull p;
            asm("mov.b64 %0, {%1,%1};" : "=l"(p) : "f"(a.x));
            ffma2(acc[ii][0], p, bv[0].x); ffma2(acc[ii][1], p, bv[0].y);
            asm("mov.b64 %0, {%1,%1};" : "=l"(p) : "f"(a.y));
            ffma2(acc[ii][0], p, bv[1].x); ffma2(acc[ii][1], p, bv[1].y);
            asm("mov.b64 %0, {%1,%1};" : "=l"(p) : "f"(a.z));
            ffma2(acc[ii][0], p, bv[2].x); ffma2(acc[ii][1], p, bv[2].y);
            asm("mov.b64 %0, {%1,%1};" : "=l"(p) : "f"(a.w));
            ffma2(acc[ii][0], p, bv[3].x); ffma2(acc[ii][1], p, bv[3].y);
        }
    }
#pragma unroll
    for (int ii = 0; ii < 4; ii++) {
        float2 v01 = unpack2(acc[ii][0]);
        float2 v23 = unpack2(acc[ii][1]);
        float* dst = g_xg0 + (m0 + mi0 + ii) * 512 + n0 + ni0;
        dst[0] = v01.x + bsm[ni0 + 0];
        dst[1] = v01.y + bsm[ni0 + 1];
        dst[2] = v23.x + bsm[ni0 + 2];
        dst[3] = v23.y + bsm[ni0 + 3];
    }
}

// ---------------- pipelined LSTM step ----------------
// layer0: blocks [0,64)   — b-tile 64, j-tile 32, 8 batches/thread
// layer1: blocks [64,192) — b-tile 32, j-tile 32, 4 batches/thread
// smem 98816 B (2 CTAs/SM: 197632 B <= 228KB)
#define LSTM_SMEM_FLOATS 24704
__global__ __launch_bounds__(256, 2) void lstm_step_kernel(int t,
                                                           const float* __restrict__ Whh0,
                                                           const float* __restrict__ Wih1,
                                                           const float* __restrict__ Whh1) {
    extern __shared__ float sm[];
    const int tid = threadIdx.x;
    const int jj = tid & 31;
    const int bg = tid >> 5;  // warp id 0..7

    if (blockIdx.x < 64) {
        if (t > 30) return;
        const int b0 = (blockIdx.x >> 2) * 64;
        const int j0 = (blockIdx.x & 3) * 32;
        float* Wp = sm;                 // 64*258
        float* hs = sm + 16512;         // [64][128]
        const float* __restrict__ hprev = g_H0[(t + 1) & 1];
        for (int idx = tid; idx < 2048; idx += 256)
            ((float4*)hs)[idx] = *(const float4*)(hprev + b0 * 128 + idx * 4);
        for (int idx = tid; idx < 128 * 128; idx += 256) {
            int k = idx & 127, r = idx >> 7;
            int q = r >> 5, j = r & 31;
            Wp[(k >> 1) * 258 + r * 2 + (k & 1)] = Whh0[(q * 128 + j0 + j) * 128 + k];
        }
        __syncthreads();
        ull acc[8][4];
#pragma unroll
        for (int i = 0; i < 8; i++)
#pragma unroll
            for (int q = 0; q < 4; q++) acc[i][q] = 0ull;
#pragma unroll 2
        for (int kp = 0; kp < 64; kp++) {
            const float* wrow = Wp + kp * 258 + jj * 2;
            const ull w0 = *(const ull*)(wrow);
            const ull w1v = *(const ull*)(wrow + 64);
            const ull w2 = *(const ull*)(wrow + 128);
            const ull w3 = *(const ull*)(wrow + 192);
#pragma unroll
            for (int i = 0; i < 8; i++) {
                const ull h = *(const ull*)(hs + (bg * 8 + i) * 128 + kp * 2);
                ffma2(acc[i][0], h, w0);
                ffma2(acc[i][1], h, w1v);
                ffma2(acc[i][2], h, w2);
                ffma2(acc[i][3], h, w3);
            }
        }
        const int j = j0 + jj;
#pragma unroll
        for (int i = 0; i < 8; i++) {
            int b = b0 + bg * 8 + i;
            const float* xg = g_xg0 + (b * NP + t) * 512;
            float2 s0 = unpack2(acc[i][0]);
            float2 s1 = unpack2(acc[i][1]);
            float2 s2 = unpack2(acc[i][2]);
            float2 s3 = unpack2(acc[i][3]);
            float gi = s0.x + s0.y + xg[j];
            float gf = s1.x + s1.y + xg[128 + j];
            float gg = s2.x + s2.y + xg[256 + j];
            float go = s3.x + s3.y + xg[384 + j];
            float c = g_C0[b * 128 + j];
            c = sigm(gf) * c + sigm(gi) * tanhf(gg);
            float h = sigm(go) * tanhf(c);
            g_C0[b * 128 + j] = c;
            g_H0[t & 1][b * 128 + j] = h;
        }
    } else {
        const int s = t - 1;
        if (s < 0) return;
        const int blk = blockIdx.x - 64;    // 0..127
        const int b0 = (blk >> 2) * 32;
        const int j0 = (blk & 3) * 32;
        float* Wp  = sm;
        float* h0s = sm + 16512;            // [32][128]
        float* h1s = h0s + 4096;            // [32][128]
        const float* __restrict__ h0in = g_H0[s & 1];
        const float* __restrict__ h1in = g_H1[(s & 1) ^ 1];
        for (int idx = tid; idx < 1024; idx += 256) {
            ((float4*)h0s)[idx] = *(const float4*)(h0in + b0 * 128 + idx * 4);
            ((float4*)h1s)[idx] = *(const float4*)(h1in + b0 * 128 + idx * 4);
        }
        for (int idx = tid; idx < 128 * 128; idx += 256) {
            int k = idx & 127, r = idx >> 7;
            int q = r >> 5, j = r & 31;
            Wp[(k >> 1) * 258 + r * 2 + (k & 1)] = Wih1[(q * 128 + j0 + j) * 128 + k];
        }
        __syncthreads();
        ull acc[4][4];
#pragma unroll
        for (int i = 0; i < 4; i++)
#pragma unroll
            for (int q = 0; q < 4; q++) acc[i][q] = 0ull;
#pragma unroll 2
        for (int kp = 0; kp < 64; kp++) {
            const float* wrow = Wp + kp * 258 + jj * 2;
            const ull w0 = *(const ull*)(wrow);
            const ull w1v = *(const ull*)(wrow + 64);
            const ull w2 = *(const ull*)(wrow + 128);
            const ull w3 = *(const ull*)(wrow + 192);
#pragma unroll
            for (int i = 0; i < 4; i++) {
                const ull h = *(const ull*)(h0s + (bg * 4 + i) * 128 + kp * 2);
                ffma2(acc[i][0], h, w0);
                ffma2(acc[i][1], h, w1v);
                ffma2(acc[i][2], h, w2);
                ffma2(acc[i][3], h, w3);
            }
        }
        __syncthreads();
        for (int idx = tid; idx < 128 * 128; idx += 256) {
            int k = idx & 127, r = idx >> 7;
            int q = r >> 5, j = r & 31;
            Wp[(k >> 1) * 258 + r * 2 + (k & 1)] = Whh1[(q * 128 + j0 + j) * 128 + k];
        }
        __syncthreads();
#pragma unroll 2
        for (int kp = 0; kp < 64; kp++) {
            const float* wrow = Wp + kp * 258 + jj * 2;
            const ull w0 = *(const ull*)(wrow);
            const ull w1v = *(const ull*)(wrow + 64);
            const ull w2 = *(const ull*)(wrow + 128);
            const ull w3 = *(const ull*)(wrow + 192);
#pragma unroll
            for (int i = 0; i < 4; i++) {
                const ull h = *(const ull*)(h1s + (bg * 4 + i) * 128 + kp * 2);
                ffma2(acc[i][0], h, w0);
                ffma2(acc[i][1], h, w1v);
                ffma2(acc[i][2], h, w2);
                ffma2(acc[i][3], h, w3);
            }
        }
        const int j = j0 + jj;
#pragma unroll
        for (int i = 0; i < 4; i++) {
            int b = b0 + bg * 4 + i;
            float2 s0 = unpack2(acc[i][0]);
            float2 s1 = unpack2(acc[i][1]);
            float2 s2 = unpack2(acc[i][2]);
            float2 s3 = unpack2(acc[i][3]);
            float gi = s0.x + s0.y + g_b1l[j];
            float gf = s1.x + s1.y + g_b1l[128 + j];
            float gg = s2.x + s2.y + g_b1l[256 + j];
            float go = s3.x + s3.y + g_b1l[384 + j];
            float c = g_C1[b * 128 + j];
            c = sigm(gf) * c + sigm(gi) * tanhf(gg);
            float h = sigm(go) * tanhf(c);
            g_C1[b * 128 + j] = c;
            g_H1[s & 1][b * 128 + j] = h;
        }
    }
}

// ---------------- classifier ----------------
__global__ __launch_bounds__(256) void fc1_kernel(const float* __restrict__ bc1) {
    __shared__ float w[128 * 64];
    __shared__ float hsm[4 * 128];
    __shared__ float bsm[64];
    const int tid = threadIdx.x;
    const int b0 = blockIdx.x * 4;
    for (int idx = tid; idx < 8192; idx += 256) w[idx] = g_Wc1t[idx];
    if (tid < 64) bsm[tid] = bc1[tid];
    for (int idx = tid; idx < 512; idx += 256) hsm[idx] = g_H1[0][b0 * 128 + idx];
    __syncthreads();
    const int o = tid & 63, bb = tid >> 6;
    float s = bsm[o];
#pragma unroll 8
    for (int k = 0; k < 128; k++) s += hsm[bb * 128 + k] * w[k * 64 + o];
    g_hid[(b0 + bb) * 64 + o] = fmaxf(s, 0.0f);
}

__global__ __launch_bounds__(256) void fc2_kernel(const float* __restrict__ Wc2,
                                                  const float* __restrict__ bc2,
                                                  float* __restrict__ out) {
    __shared__ float w[11 * 64];
    __shared__ float bsm[11];
    __shared__ float hs[16 * 64];
    const int tid = threadIdx.x;
    const int b0 = blockIdx.x * 16;
    for (int idx = tid; idx < 704; idx += 256) w[idx] = Wc2[idx];
    if (tid < 11) bsm[tid] = bc2[tid];
    for (int idx = tid; idx < 1024; idx += 256) hs[idx] = g_hid[b0 * 64 + idx];
    __syncthreads();
    if (tid < 176) {
        int bb = tid / 11, c = tid - bb * 11;
        float s = bsm[c];
#pragma unroll 8
        for (int k = 0; k < 64; k++) s += hs[bb * 64 + k] * w[c * 64 + k];
        out[(b0 + bb) * 11 + c] = s;
    }
}

// ---------------- launch ----------------
extern "C" void kernel_launch(void* const* d_in, const int* in_sizes, int n_in,
                              void* d_out, int out_size) {
    const float* I    = (const float*)d_in[0];
    const float* Q    = (const float*)d_in[1];
    const float* E    = (const float*)d_in[2];
    const float* Wn1  = (const float*)d_in[3];
    const float* bn1  = (const float*)d_in[4];
    const float* Ws1  = (const float*)d_in[5];
    const float* bs1  = (const float*)d_in[6];
    const float* Wn2  = (const float*)d_in[7];
    const float* bn2  = (const float*)d_in[8];
    const float* Ws2  = (const float*)d_in[9];
    const float* bs2  = (const float*)d_in[10];
    const float* Wih0 = (const float*)d_in[11];
    const float* Whh0 = (const float*)d_in[12];
    const float* bih0 = (const float*)d_in[13];
    const float* bhh0 = (const float*)d_in[14];
    const float* Wih1 = (const float*)d_in[15];
    const float* Whh1 = (const float*)d_in[16];
    const float* bih1 = (const float*)d_in[17];
    const float* bhh1 = (const float*)d_in[18];
    const float* Wc1  = (const float*)d_in[19];
    const float* bc1  = (const float*)d_in[20];
    const float* Wc2  = (const float*)d_in[21];
    const float* bc2  = (const float*)d_in[22];
    float* out = (float*)d_out;

    const size_t gnn_smem  = GNN_SMEM_FLOATS * sizeof(float);   // 109568 B
    const size_t lstm_smem = LSTM_SMEM_FLOATS * sizeof(float);  // 98816 B
    cudaFuncSetAttribute(gnn_kernel, cudaFuncAttributeMaxDynamicSharedMemorySize, (int)gnn_smem);
    cudaFuncSetAttribute(lstm_step_kernel, cudaFuncAttributeMaxDynamicSharedMemorySize, (int)lstm_smem);
    cudaFuncSetAttribute(gnn_kernel, cudaFuncAttributePreferredSharedMemoryCarveout, 100);
    cudaFuncSetAttribute(lstm_step_kernel, cudaFuncAttributePreferredSharedMemoryCarveout, 100);

    // launch order chosen so gnn_kernel lands in the ncu capture slot (4th launch)
    prep_kernel<<<1, 256>>>(E, Wn1, bn1, Ws1, bs1, Wn2, bn2, Ws2, bs2,
                            bih0, bhh0, bih1, bhh1);
    prep_big_kernel<<<128, 256>>>(Wih0, Wc1);
    zero_kernel<<<512, 256>>>();
    gnn_kernel<<<(NBATCH * NP) / 2, 256, gnn_smem>>>(I, Q);
    xg0_kernel<<<dim3((NBATCH * NP) / 64, 8), 256>>>();
    for (int t = 0; t < 32; t++)
        lstm_step_kernel<<<192, 256, lstm_smem>>>(t, Whh0, Wih1, Whh1);
    fc1_kernel<<<NBATCH / 4, 256>>>(bc1);
    fc2_kernel<<<NBATCH / 16, 256>>>(Wc2, bc2, out);
    (void)in_sizes; (void)n_in; (void)out_size;
}

// round 12
// speedup vs baseline: 1.0575x; 1.0575x over previous
#include <cuda_runtime.h>
#include <cuda_bf16.h>
#include <math.h>

// ---------------- problem constants ----------------
#define NBATCH 1024
#define NP     31
#define RHD    128
#define NC     11

typedef unsigned long long ull;

// ---------------- helpers ----------------
__device__ __forceinline__ void ffma2(ull& d, ull a, ull b) {
    asm("fma.rn.f32x2 %0, %1, %2, %0;" : "+l"(d) : "l"(a), "l"(b));
}
__device__ __forceinline__ float2 unpack2(ull v) {
    float2 r; asm("mov.b64 {%0,%1}, %2;" : "=f"(r.x), "=f"(r.y) : "l"(v)); return r;
}
__device__ __forceinline__ float sigm(float x) { return 1.0f / (1.0f + expf(-x)); }
__device__ __forceinline__ unsigned smem_u32(const void* p) {
    unsigned r;
    asm("{ .reg .u64 t; cvta.to.shared.u64 t, %1; cvt.u32.u64 %0, t; }" : "=r"(r) : "l"(p));
    return r;
}
__device__ __forceinline__ void ldm4(unsigned* r, unsigned addr) {
    asm volatile("ldmatrix.sync.aligned.m8n8.x4.shared.b16 {%0,%1,%2,%3}, [%4];"
                 : "=r"(r[0]), "=r"(r[1]), "=r"(r[2]), "=r"(r[3]) : "r"(addr));
}
__device__ __forceinline__ void mma_bf16(float* c, const unsigned* a, const unsigned* b) {
    asm volatile(
        "mma.sync.aligned.m16n8k16.row.col.f32.bf16.bf16.f32 "
        "{%0,%1,%2,%3}, {%4,%5,%6,%7}, {%8,%9}, {%0,%1,%2,%3};"
        : "+f"(c[0]), "+f"(c[1]), "+f"(c[2]), "+f"(c[3])
        : "r"(a[0]), "r"(a[1]), "r"(a[2]), "r"(a[3]), "r"(b[0]), "r"(b[1]));
}
__device__ __forceinline__ unsigned pack_bf16x2(float lo, float hi) {
    unsigned short l = __bfloat16_as_ushort(__float2bfloat16(lo));
    unsigned short h = __bfloat16_as_ushort(__float2bfloat16(hi));
    return (unsigned)l | ((unsigned)h << 16);
}

// ---------------- device scratch ----------------
__device__ float g_awT[17 * 64];
__device__ float g_awT2[17 * 64 * 2];
__device__ float g_b1[64];
__device__ float g_b2[64];
__device__ float g_w1[256];
__device__ uint4 g_Bh4[1088];             // padded bf16 Bh [64][136] (17408 B)
__device__ uint4 g_Bl4[1088];             // padded bf16 Bl [64][136]
__device__ float g_b0c[512];
__device__ float g_b1l[512];
__device__ float g_Wih0t[64 * 512];
__device__ float g_Wc1t[128 * 64];
__device__ float g_feats[NBATCH * NP * 64];
__device__ float g_xg0[NBATCH * NP * 512];
__device__ float g_H0[2][NBATCH * RHD];
__device__ float g_C0[NBATCH * RHD];
__device__ float g_H1[2][NBATCH * RHD];
__device__ float g_C1[NBATCH * RHD];
__device__ float g_hid[NBATCH * 64];

// ---------------- prep (small, single block) ----------------
__global__ void prep_kernel(const float* __restrict__ E,
                            const float* __restrict__ Wn1, const float* __restrict__ bn1,
                            const float* __restrict__ Ws1, const float* __restrict__ bs1,
                            const float* __restrict__ Wn2, const float* __restrict__ bn2,
                            const float* __restrict__ Ws2, const float* __restrict__ bs2,
                            const float* __restrict__ bih0, const float* __restrict__ bhh0,
                            const float* __restrict__ bih1, const float* __restrict__ bhh1) {
    const int tid = threadIdx.x;
    if (tid < 64) {
        float row[17];
        float deg = 0.0f;
#pragma unroll
        for (int k = 0; k < 17; k++) {
            int j = tid - 8 + k;
            float a = 0.0f;
            if (j >= 0 && j < 64 && j != tid) a = 1.0f / (1.0f + expf(-E[tid * 64 + j]));
            row[k] = a;
            deg += a;
        }
        float inv = deg > 0.0f ? 1.0f / deg : 0.0f;
#pragma unroll
        for (int k = 0; k < 17; k++) g_awT[k * 64 + tid] = row[k] * inv;
        g_b1[tid] = bs1[tid] + bn1[tid];
        g_b2[tid] = bs2[tid] + bn2[tid];
        g_w1[tid]       = Ws1[tid * 2 + 0];
        g_w1[64 + tid]  = Ws1[tid * 2 + 1];
        g_w1[128 + tid] = Wn1[tid * 2 + 0];
        g_w1[192 + tid] = Wn1[tid * 2 + 1];
    }
    __syncthreads();
    for (int idx = tid; idx < 17 * 64; idx += 256) {
        float v = g_awT[idx];
        g_awT2[idx * 2 + 0] = v;
        g_awT2[idx * 2 + 1] = v;
    }
    // B = [Ws2 | Wn2] split into bf16 hi/lo, padded [64][136]
    __nv_bfloat16* Bh = (__nv_bfloat16*)g_Bh4;
    __nv_bfloat16* Bl = (__nv_bfloat16*)g_Bl4;
    for (int idx = tid; idx < 64 * 136; idx += 256) {   // zero pad first
        Bh[idx] = __float2bfloat16(0.0f);
        Bl[idx] = __float2bfloat16(0.0f);
    }
    __syncthreads();
    for (int idx = tid; idx < 64 * 128; idx += 256) {
        int o = idx >> 7, k = idx & 127;
        float w = (k < 64) ? Ws2[o * 64 + k] : Wn2[o * 64 + (k - 64)];
        __nv_bfloat16 hi = __float2bfloat16(w);
        __nv_bfloat16 lo = __float2bfloat16(w - __bfloat162float(hi));
        Bh[o * 136 + k] = hi;
        Bl[o * 136 + k] = lo;
    }
    for (int idx = tid; idx < 512; idx += 256) {
        g_b0c[idx] = bih0[idx] + bhh0[idx];
        g_b1l[idx] = bih1[idx] + bhh1[idx];
    }
}

// ---------------- prep (big transposes, multi-block) ----------------
__global__ void prep_big_kernel(const float* __restrict__ Wih0,
                                const float* __restrict__ Wc1) {
    int idx = blockIdx.x * blockDim.x + threadIdx.x;
    if (idx < 512 * 64) {
        int n = idx >> 6, k = idx & 63;
        g_Wih0t[k * 512 + n] = Wih0[idx];
    }
    if (idx < 64 * 128) {
        int o = idx >> 7, k = idx & 127;
        g_Wc1t[k * 64 + o] = Wc1[idx];
    }
}

__global__ void zero_kernel() {
    int i = blockIdx.x * blockDim.x + threadIdx.x;
    if (i < NBATCH * RHD) {
        g_H0[1][i] = 0.0f;
        g_C0[i]    = 0.0f;
        g_H1[1][i] = 0.0f;
        g_C1[i]    = 0.0f;
    }
}

// ---------------- fused GNN: 2 patches/CTA, mma.sync bf16-split SAGE2 GEMM ----------------
// smem byte offsets:
#define OFF_X1A   0          // 16384
#define OFF_N1A   16384
#define OFF_X1B   32768
#define OFF_N1B   49152
#define OFF_AH    65536      // [128][136] bf16 = 34816
#define OFF_AL    100352
#define OFF_BH    135168     // [64][136] bf16 = 17408
#define OFF_BL    152576
#define OFF_AWT2  169984     // 2176 floats = 8704
#define OFF_X0    178688
#define OFF_N0    179200
#define OFF_W1    179712
#define OFF_B1S   180736
#define OFF_B2S   180992
#define GNN_SMEM_BYTES 181248
__global__ __launch_bounds__(256) void gnn_kernel(const float* __restrict__ I,
                                                  const float* __restrict__ Q) {
    extern __shared__ char smc[];
    float* const x1a  = (float*)(smc + OFF_X1A);
    float* const n1a  = (float*)(smc + OFF_N1A);
    float* const x1b  = (float*)(smc + OFF_X1B);
    float* const n1b  = (float*)(smc + OFF_N1B);
    float* const awT2 = (float*)(smc + OFF_AWT2);
    float* const x0   = (float*)(smc + OFF_X0);
    float* const n0   = (float*)(smc + OFF_N0);
    float* const w1   = (float*)(smc + OFF_W1);
    float* const b1s  = (float*)(smc + OFF_B1S);
    float* const b2s  = (float*)(smc + OFF_B2S);

    const int tid = threadIdx.x;
    const int wid = tid >> 5;
    const int lid = tid & 31;
    const unsigned sbase = smem_u32(smc);

    // B tiles + tables into smem
    for (int idx = tid; idx < 1088; idx += 256) {
        ((uint4*)(smc + OFF_BH))[idx] = g_Bh4[idx];
        ((uint4*)(smc + OFF_BL))[idx] = g_Bl4[idx];
    }
    for (int idx = tid; idx < 2176; idx += 256) awT2[idx] = g_awT2[idx];
    w1[tid] = g_w1[tid];
    if (tid < 64) {
        b1s[tid] = g_b1[tid];
        b2s[tid] = g_b2[tid];
    }

    const int gp0 = blockIdx.x * 2;

    // ---- per-patch phases: x0 -> neigh0 -> sage1 -> conv ----
#pragma unroll 1
    for (int pp = 0; pp < 2; pp++) {
        const int gp = gp0 + pp;
        const int b  = gp / NP;
        const int p  = gp - b * NP;
        float* x1 = pp ? x1b : x1a;
        float* n1 = pp ? n1b : n1a;
        __syncthreads();
        if (tid < 64) {
            int pos = b * 1024 + p * 32 + tid;
            x0[tid * 2 + 0] = I[pos];
            x0[tid * 2 + 1] = Q[pos];
        }
        __syncthreads();

        if (tid < 128) {
            int i = tid >> 1, dd = tid & 1;
            float s = 0.0f;
#pragma unroll
            for (int k = 0; k < 17; k++) {
                int j = i - 8 + k;
                j = max(0, min(63, j));
                s += awT2[(k * 64 + i) * 2] * x0[j * 2 + dd];
            }
            n0[tid] = s;
        }
        __syncthreads();

        // SAGE layer 1
        {
            const int o = tid & 63, ig = tid >> 6;
            const float ws0 = w1[o], ws1 = w1[64 + o], wn0 = w1[128 + o], wn1 = w1[192 + o];
            const float bb = b1s[o];
#pragma unroll
            for (int ii = 0; ii < 16; ii++) {
                int i = ig * 16 + ii;
                float v = bb + x0[i * 2] * ws0 + x0[i * 2 + 1] * ws1
                             + n0[i * 2] * wn0 + n0[i * 2 + 1] * wn1;
                x1[i * 64 + o] = fmaxf(v, 0.0f);
            }
        }
        __syncthreads();

        // banded conv -> n1 (f32x2, sliding register window)
        {
            const int dp = tid & 31;
            const int ig = tid >> 5;
            const int i0 = ig * 8;
            ull xw[24];
#pragma unroll
            for (int w = 0; w < 24; w++) {
                int j = i0 - 8 + w;
                j = max(0, min(63, j));
                xw[w] = *(const ull*)(x1 + j * 64 + 2 * dp);
            }
            ull acc[8];
#pragma unroll
            for (int ii = 0; ii < 8; ii++) acc[ii] = 0ull;
#pragma unroll
            for (int k = 0; k < 17; k++) {
#pragma unroll
                for (int ii = 0; ii < 8; ii += 2) {
                    const ulonglong2 aw = *(const ulonglong2*)(awT2 + (k * 64 + i0 + ii) * 2);
                    ffma2(acc[ii],     aw.x, xw[ii + k]);
                    ffma2(acc[ii + 1], aw.y, xw[ii + 1 + k]);
                }
            }
#pragma unroll
            for (int ii = 0; ii < 8; ii++)
                *(ull*)(n1 + (i0 + ii) * 64 + 2 * dp) = acc[ii];
        }
    }
    __syncthreads();

    // ---- convert x1/n1 fp32 -> Ah/Al bf16 [128][136] (row m = patch*64+node, K=128) ----
    {
        unsigned* Ah32 = (unsigned*)(smc + OFF_AH);
        unsigned* Al32 = (unsigned*)(smc + OFF_AL);
        for (int idx = tid; idx < 128 * 64; idx += 256) {
            const int m = idx >> 6, kp = idx & 63;      // k pair = {2kp, 2kp+1}
            const int pa = m >> 6, i = m & 63;
            const float* src = (kp < 32) ? (pa ? x1b : x1a) : (pa ? n1b : n1a);
            const float2 v = *(const float2*)(src + i * 64 + (kp & 31) * 2);
            const float h0 = __bfloat162float(__float2bfloat16(v.x));
            const float h1 = __bfloat162float(__float2bfloat16(v.y));
            // (m*136 + kp*2) bf16 index / 2 = u32 index (m*136 even since 136 even? 136*m even, kp*2 even -> /2 ok)
            const int u32i = (m * 136 + kp * 2) >> 1;
            Ah32[u32i] = pack_bf16x2(v.x, v.y);
            Al32[u32i] = pack_bf16x2(v.x - h0, v.y - h1);
        }
    }
    __syncthreads();

    // ---- mma.sync GEMM: D[128x64] = Ah*B^T(h) + Ah*B^T(l) + Al*B^T(h) ----
    float* stage = (float*)smc;   // fp32 buffers dead; reuse as [128][65] stage
    {
        const int m0 = wid * 16;
        const unsigned rA = (unsigned)(m0 + (lid & 7) + ((lid >> 3) & 1) * 8);
        const unsigned cA = (unsigned)((lid >> 4) * 8);
        unsigned aAddr = sbase + OFF_AH + (rA * 136 + cA) * 2;
        const unsigned rBp = (unsigned)((lid >> 4) * 8 + (lid & 7));
        const unsigned cBp = (unsigned)(((lid >> 3) & 1) * 8);
        unsigned bAddr = sbase + OFF_BH + (rBp * 136 + cBp) * 2;

        float acc[8][4];
#pragma unroll
        for (int nt = 0; nt < 8; nt++)
#pragma unroll
            for (int c = 0; c < 4; c++) acc[nt][c] = 0.0f;

#pragma unroll 1
        for (int ks = 0; ks < 8; ks++) {
            unsigned aH[4], aL[4], bH[16], bL[16];
            ldm4(aH, aAddr);
            ldm4(aL, aAddr + (OFF_AL - OFF_AH));
#pragma unroll
            for (int pq = 0; pq < 4; pq++) {
                ldm4(bH + 4 * pq, bAddr + pq * 4352u);
                ldm4(bL + 4 * pq, bAddr + pq * 4352u + (OFF_BL - OFF_BH));
            }
#pragma unroll
            for (int nt = 0; nt < 8; nt++) {
                mma_bf16(acc[nt], aH, bH + nt * 2);
                mma_bf16(acc[nt], aH, bL + nt * 2);
                mma_bf16(acc[nt], aL, bH + nt * 2);
            }
            aAddr += 32;
            bAddr += 32;
        }

        // epilogue: bias + relu into stage[m][o], pitch 65
        const int r = lid >> 2, cp = (lid & 3) * 2;
#pragma unroll
        for (int nt = 0; nt < 8; nt++) {
            const int o = nt * 8 + cp;
            const float bb0 = b2s[o], bb1 = b2s[o + 1];
            stage[(m0 + r) * 65 + o]         = fmaxf(acc[nt][0] + bb0, 0.0f);
            stage[(m0 + r) * 65 + o + 1]     = fmaxf(acc[nt][1] + bb1, 0.0f);
            stage[(m0 + 8 + r) * 65 + o]     = fmaxf(acc[nt][2] + bb0, 0.0f);
            stage[(m0 + 8 + r) * 65 + o + 1] = fmaxf(acc[nt][3] + bb1, 0.0f);
        }
    }
    __syncthreads();
    if (tid < 128) {
        const int pa = tid >> 6, o = tid & 63;
        float s = 0.0f;
#pragma unroll
        for (int i = 0; i < 64; i++) s += stage[(pa * 64 + i) * 65 + o];
        g_feats[(gp0 + pa) * 64 + o] = s;
    }
}

// ---------------- xg0 = feats @ Wih0^T + bias : [31744 x 512], K=64 ----------------
__global__ __launch_bounds__(256) void xg0_kernel() {
    __shared__ float As[64 * 64];
    __shared__ float Bs[64 * 64];
    __shared__ float bsm[64];
    const int m0 = blockIdx.x * 64;
    const int n0 = blockIdx.y * 64;
    const int tid = threadIdx.x;
    for (int idx = tid; idx < 1024; idx += 256)
        ((float4*)As)[idx] = *(const float4*)(g_feats + (m0 + (idx >> 4)) * 64 + (idx & 15) * 4);
    for (int idx = tid; idx < 1024; idx += 256)
        ((float4*)Bs)[idx] = *(const float4*)(g_Wih0t + (idx >> 4) * 512 + n0 + (idx & 15) * 4);
    if (tid < 64) bsm[tid] = g_b0c[n0 + tid];
    __syncthreads();
    const int mi0 = (tid >> 4) * 4;
    const int ni0 = (tid & 15) * 4;
    ull acc[4][2];
#pragma unroll
    for (int ii = 0; ii < 4; ii++) { acc[ii][0] = 0ull; acc[ii][1] = 0ull; }
#pragma unroll 2
    for (int k = 0; k < 64; k += 4) {
        ulonglong2 bv[4];
#pragma unroll
        for (int kk = 0; kk < 4; kk++) bv[kk] = *(const ulonglong2*)(Bs + (k + kk) * 64 + ni0);
#pragma unroll
        for (int ii = 0; ii < 4; ii++) {
            const float4 a = *(const float4*)(As + (mi0 + ii) * 64 + k);
            ull p;
            asm("mov.b64 %0, {%1,%1};" : "=l"(p) : "f"(a.x));
            ffma2(acc[ii][0], p, bv[0].x); ffma2(acc[ii][1], p, bv[0].y);
            asm("mov.b64 %0, {%1,%1};" : "=l"(p) : "f"(a.y));
            ffma2(acc[ii][0], p, bv[1].x); ffma2(acc[ii][1], p, bv[1].y);
            asm("mov.b64 %0, {%1,%1};" : "=l"(p) : "f"(a.z));
            ffma2(acc[ii][0], p, bv[2].x); ffma2(acc[ii][1], p, bv[2].y);
            asm("mov.b64 %0, {%1,%1};" : "=l"(p) : "f"(a.w));
            ffma2(acc[ii][0], p, bv[3].x); ffma2(acc[ii][1], p, bv[3].y);
        }
    }
#pragma unroll
    for (int ii = 0; ii < 4; ii++) {
        float2 v01 = unpack2(acc[ii][0]);
        float2 v23 = unpack2(acc[ii][1]);
        float* dst = g_xg0 + (m0 + mi0 + ii) * 512 + n0 + ni0;
        dst[0] = v01.x + bsm[ni0 + 0];
        dst[1] = v01.y + bsm[ni0 + 1];
        dst[2] = v23.x + bsm[ni0 + 2];
        dst[3] = v23.y + bsm[ni0 + 3];
    }
}

// ---------------- pipelined LSTM step (R8 config) ----------------
#define LSTM_SMEM_FLOATS 24704
__global__ __launch_bounds__(256) void lstm_step_kernel(int t,
                                                        const float* __restrict__ Whh0,
                                                        const float* __restrict__ Wih1,
                                                        const float* __restrict__ Whh1) {
    extern __shared__ float sm[];
    const int tid = threadIdx.x;
    const int jj = tid & 31;
    const int bg = tid >> 5;

    if (blockIdx.x < 64) {
        if (t > 30) return;
        const int b0 = (blockIdx.x >> 2) * 64;
        const int j0 = (blockIdx.x & 3) * 32;
        float* Wp = sm;
        float* hs = sm + 16512;
        const float* __restrict__ hprev = g_H0[(t + 1) & 1];
        for (int idx = tid; idx < 2048; idx += 256)
            ((float4*)hs)[idx] = *(const float4*)(hprev + b0 * 128 + idx * 4);
        for (int idx = tid; idx < 128 * 128; idx += 256) {
            int k = idx & 127, r = idx >> 7;
            int q = r >> 5, j = r & 31;
            Wp[(k >> 1) * 258 + r * 2 + (k & 1)] = Whh0[(q * 128 + j0 + j) * 128 + k];
        }
        __syncthreads();
        ull acc[8][4];
#pragma unroll
        for (int i = 0; i < 8; i++)
#pragma unroll
            for (int q = 0; q < 4; q++) acc[i][q] = 0ull;
#pragma unroll 2
        for (int kp = 0; kp < 64; kp++) {
            const float* wrow = Wp + kp * 258 + jj * 2;
            const ull w0 = *(const ull*)(wrow);
            const ull w1v = *(const ull*)(wrow + 64);
            const ull w2 = *(const ull*)(wrow + 128);
            const ull w3 = *(const ull*)(wrow + 192);
#pragma unroll
            for (int i = 0; i < 8; i++) {
                const ull h = *(const ull*)(hs + (bg * 8 + i) * 128 + kp * 2);
                ffma2(acc[i][0], h, w0);
                ffma2(acc[i][1], h, w1v);
                ffma2(acc[i][2], h, w2);
                ffma2(acc[i][3], h, w3);
            }
        }
        const int j = j0 + jj;
#pragma unroll
        for (int i = 0; i < 8; i++) {
            int b = b0 + bg * 8 + i;
            const float* xg = g_xg0 + (b * NP + t) * 512;
            float2 s0 = unpack2(acc[i][0]);
            float2 s1 = unpack2(acc[i][1]);
            float2 s2 = unpack2(acc[i][2]);
            float2 s3 = unpack2(acc[i][3]);
            float gi = s0.x + s0.y + xg[j];
            float gf = s1.x + s1.y + xg[128 + j];
            float gg = s2.x + s2.y + xg[256 + j];
            float go = s3.x + s3.y + xg[384 + j];
            float c = g_C0[b * 128 + j];
            c = sigm(gf) * c + sigm(gi) * tanhf(gg);
            float h = sigm(go) * tanhf(c);
            g_C0[b * 128 + j] = c;
            g_H0[t & 1][b * 128 + j] = h;
        }
    } else {
        const int s = t - 1;
        if (s < 0) return;
        const int blk = blockIdx.x - 64;
        const int b0 = (blk >> 2) * 32;
        const int j0 = (blk & 3) * 32;
        float* Wp  = sm;
        float* h0s = sm + 16512;
        float* h1s = h0s + 4096;
        const float* __restrict__ h0in = g_H0[s & 1];
        const float* __restrict__ h1in = g_H1[(s & 1) ^ 1];
        for (int idx = tid; idx < 1024; idx += 256) {
            ((float4*)h0s)[idx] = *(const float4*)(h0in + b0 * 128 + idx * 4);
            ((float4*)h1s)[idx] = *(const float4*)(h1in + b0 * 128 + idx * 4);
        }
        for (int idx = tid; idx < 128 * 128; idx += 256) {
            int k = idx & 127, r = idx >> 7;
            int q = r >> 5, j = r & 31;
            Wp[(k >> 1) * 258 + r * 2 + (k & 1)] = Wih1[(q * 128 + j0 + j) * 128 + k];
        }
        __syncthreads();
        ull acc[4][4];
#pragma unroll
        for (int i = 0; i < 4; i++)
#pragma unroll
            for (int q = 0; q < 4; q++) acc[i][q] = 0ull;
#pragma unroll 2
        for (int kp = 0; kp < 64; kp++) {
            const float* wrow = Wp + kp * 258 + jj * 2;
            const ull w0 = *(const ull*)(wrow);
            const ull w1v = *(const ull*)(wrow + 64);
            const ull w2 = *(const ull*)(wrow + 128);
            const ull w3 = *(const ull*)(wrow + 192);
#pragma unroll
            for (int i = 0; i < 4; i++) {
                const ull h = *(const ull*)(h0s + (bg * 4 + i) * 128 + kp * 2);
                ffma2(acc[i][0], h, w0);
                ffma2(acc[i][1], h, w1v);
                ffma2(acc[i][2], h, w2);
                ffma2(acc[i][3], h, w3);
            }
        }
        __syncthreads();
        for (int idx = tid; idx < 128 * 128; idx += 256) {
            int k = idx & 127, r = idx >> 7;
            int q = r >> 5, j = r & 31;
            Wp[(k >> 1) * 258 + r * 2 + (k & 1)] = Whh1[(q * 128 + j0 + j) * 128 + k];
        }
        __syncthreads();
#pragma unroll 2
        for (int kp = 0; kp < 64; kp++) {
            const float* wrow = Wp + kp * 258 + jj * 2;
            const ull w0 = *(const ull*)(wrow);
            const ull w1v = *(const ull*)(wrow + 64);
            const ull w2 = *(const ull*)(wrow + 128);
            const ull w3 = *(const ull*)(wrow + 192);
#pragma unroll
            for (int i = 0; i < 4; i++) {
                const ull h = *(const ull*)(h1s + (bg * 4 + i) * 128 + kp * 2);
                ffma2(acc[i][0], h, w0);
                ffma2(acc[i][1], h, w1v);
                ffma2(acc[i][2], h, w2);
                ffma2(acc[i][3], h, w3);
            }
        }
        const int j = j0 + jj;
#pragma unroll
        for (int i = 0; i < 4; i++) {
            int b = b0 + bg * 4 + i;
            float2 s0 = unpack2(acc[i][0]);
            float2 s1 = unpack2(acc[i][1]);
            float2 s2 = unpack2(acc[i][2]);
            float2 s3 = unpack2(acc[i][3]);
            float gi = s0.x + s0.y + g_b1l[j];
            float gf = s1.x + s1.y + g_b1l[128 + j];
            float gg = s2.x + s2.y + g_b1l[256 + j];
            float go = s3.x + s3.y + g_b1l[384 + j];
            float c = g_C1[b * 128 + j];
            c = sigm(gf) * c + sigm(gi) * tanhf(gg);
            float h = sigm(go) * tanhf(c);
            g_C1[b * 128 + j] = c;
            g_H1[s & 1][b * 128 + j] = h;
        }
    }
}

// ---------------- classifier ----------------
__global__ __launch_bounds__(256) void fc1_kernel(const float* __restrict__ bc1) {
    __shared__ float w[128 * 64];
    __shared__ float hsm[4 * 128];
    __shared__ float bsm[64];
    const int tid = threadIdx.x;
    const int b0 = blockIdx.x * 4;
    for (int idx = tid; idx < 8192; idx += 256) w[idx] = g_Wc1t[idx];
    if (tid < 64) bsm[tid] = bc1[tid];
    for (int idx = tid; idx < 512; idx += 256) hsm[idx] = g_H1[0][b0 * 128 + idx];
    __syncthreads();
    const int o = tid & 63, bb = tid >> 6;
    float s = bsm[o];
#pragma unroll 8
    for (int k = 0; k < 128; k++) s += hsm[bb * 128 + k] * w[k * 64 + o];
    g_hid[(b0 + bb) * 64 + o] = fmaxf(s, 0.0f);
}

__global__ __launch_bounds__(256) void fc2_kernel(const float* __restrict__ Wc2,
                                                  const float* __restrict__ bc2,
                                                  float* __restrict__ out) {
    __shared__ float w[11 * 64];
    __shared__ float bsm[11];
    __shared__ float hs[16 * 64];
    const int tid = threadIdx.x;
    const int b0 = blockIdx.x * 16;
    for (int idx = tid; idx < 704; idx += 256) w[idx] = Wc2[idx];
    if (tid < 11) bsm[tid] = bc2[tid];
    for (int idx = tid; idx < 1024; idx += 256) hs[idx] = g_hid[b0 * 64 + idx];
    __syncthreads();
    if (tid < 176) {
        int bb = tid / 11, c = tid - bb * 11;
        float s = bsm[c];
#pragma unroll 8
        for (int k = 0; k < 64; k++) s += hs[bb * 64 + k] * w[c * 64 + k];
        out[(b0 + bb) * 11 + c] = s;
    }
}

// ---------------- launch ----------------
extern "C" void kernel_launch(void* const* d_in, const int* in_sizes, int n_in,
                              void* d_out, int out_size) {
    const float* I    = (const float*)d_in[0];
    const float* Q    = (const float*)d_in[1];
    const float* E    = (const float*)d_in[2];
    const float* Wn1  = (const float*)d_in[3];
    const float* bn1  = (const float*)d_in[4];
    const float* Ws1  = (const float*)d_in[5];
    const float* bs1  = (const float*)d_in[6];
    const float* Wn2  = (const float*)d_in[7];
    const float* bn2  = (const float*)d_in[8];
    const float* Ws2  = (const float*)d_in[9];
    const float* bs2  = (const float*)d_in[10];
    const float* Wih0 = (const float*)d_in[11];
    const float* Whh0 = (const float*)d_in[12];
    const float* bih0 = (const float*)d_in[13];
    const float* bhh0 = (const float*)d_in[14];
    const float* Wih1 = (const float*)d_in[15];
    const float* Whh1 = (const float*)d_in[16];
    const float* bih1 = (const float*)d_in[17];
    const float* bhh1 = (const float*)d_in[18];
    const float* Wc1  = (const float*)d_in[19];
    const float* bc1  = (const float*)d_in[20];
    const float* Wc2  = (const float*)d_in[21];
    const float* bc2  = (const float*)d_in[22];
    float* out = (float*)d_out;

    const size_t lstm_smem = LSTM_SMEM_FLOATS * sizeof(float);  // 98816 B
    cudaFuncSetAttribute(gnn_kernel, cudaFuncAttributeMaxDynamicSharedMemorySize, GNN_SMEM_BYTES);
    cudaFuncSetAttribute(lstm_step_kernel, cudaFuncAttributeMaxDynamicSharedMemorySize, (int)lstm_smem);

    // launch order chosen so gnn_kernel lands in the ncu capture slot (4th launch)
    prep_kernel<<<1, 256>>>(E, Wn1, bn1, Ws1, bs1, Wn2, bn2, Ws2, bs2,
                            bih0, bhh0, bih1, bhh1);
    prep_big_kernel<<<128, 256>>>(Wih0, Wc1);
    zero_kernel<<<512, 256>>>();
    gnn_kernel<<<(NBATCH * NP) / 2, 256, GNN_SMEM_BYTES>>>(I, Q);
    xg0_kernel<<<dim3((NBATCH * NP) / 64, 8), 256>>>();
    for (int t = 0; t < 32; t++)
        lstm_step_kernel<<<192, 256, lstm_smem>>>(t, Whh0, Wih1, Whh1);
    fc1_kernel<<<NBATCH / 4, 256>>>(bc1);
    fc2_kernel<<<NBATCH / 16, 256>>>(Wc2, bc2, out);
    (void)in_sizes; (void)n_in; (void)out_size;
}

// round 13
// speedup vs baseline: 1.1183x; 1.0576x over previous
#include <cuda_runtime.h>
#include <cuda_bf16.h>
#include <math.h>

// ---------------- problem constants ----------------
#define NBATCH 1024
#define NP     31
#define RHD    128
#define NC     11

typedef unsigned long long ull;

// ---------------- helpers ----------------
__device__ __forceinline__ void ffma2(ull& d, ull a, ull b) {
    asm("fma.rn.f32x2 %0, %1, %2, %0;" : "+l"(d) : "l"(a), "l"(b));
}
__device__ __forceinline__ float2 unpack2(ull v) {
    float2 r; asm("mov.b64 {%0,%1}, %2;" : "=f"(r.x), "=f"(r.y) : "l"(v)); return r;
}
__device__ __forceinline__ float sigm(float x) { return 1.0f / (1.0f + expf(-x)); }
__device__ __forceinline__ unsigned smem_u32(const void* p) {
    unsigned r;
    asm("{ .reg .u64 t; cvta.to.shared.u64 t, %1; cvt.u32.u64 %0, t; }" : "=r"(r) : "l"(p));
    return r;
}
__device__ __forceinline__ void ldm4(unsigned* r, unsigned addr) {
    asm volatile("ldmatrix.sync.aligned.m8n8.x4.shared.b16 {%0,%1,%2,%3}, [%4];"
                 : "=r"(r[0]), "=r"(r[1]), "=r"(r[2]), "=r"(r[3]) : "r"(addr));
}
__device__ __forceinline__ void mma_bf16(float* c, const unsigned* a, const unsigned* b) {
    asm volatile(
        "mma.sync.aligned.m16n8k16.row.col.f32.bf16.bf16.f32 "
        "{%0,%1,%2,%3}, {%4,%5,%6,%7}, {%8,%9}, {%0,%1,%2,%3};"
        : "+f"(c[0]), "+f"(c[1]), "+f"(c[2]), "+f"(c[3])
        : "r"(a[0]), "r"(a[1]), "r"(a[2]), "r"(a[3]), "r"(b[0]), "r"(b[1]));
}
__device__ __forceinline__ unsigned pack_bf16x2(float lo, float hi) {
    unsigned short l = __bfloat16_as_ushort(__float2bfloat16(lo));
    unsigned short h = __bfloat16_as_ushort(__float2bfloat16(hi));
    return (unsigned)l | ((unsigned)h << 16);
}

// ---------------- device scratch ----------------
__device__ float g_awT[17 * 64];
__device__ float g_awT2[17 * 64 * 2];
__device__ float g_b1[64];
__device__ float g_b2[64];
__device__ float g_w1[256];
__device__ uint4 g_Bh4[1088];             // padded bf16 Bh [64][136] (17408 B)
__device__ uint4 g_Bl4[1088];             // padded bf16 Bl [64][136]
__device__ float g_b0c[512];
__device__ float g_b1l[512];
__device__ float g_Wih0t[64 * 512];
__device__ float g_Wc1t[128 * 64];
__device__ float g_feats[NBATCH * NP * 64];
__device__ float g_xg0[NBATCH * NP * 512];
__device__ float g_H0[2][NBATCH * RHD];
__device__ float g_C0[NBATCH * RHD];
__device__ float g_H1[2][NBATCH * RHD];
__device__ float g_C1[NBATCH * RHD];
__device__ float g_hid[NBATCH * 64];

// ---------------- prep (small, single block) ----------------
__global__ void prep_kernel(const float* __restrict__ E,
                            const float* __restrict__ Wn1, const float* __restrict__ bn1,
                            const float* __restrict__ Ws1, const float* __restrict__ bs1,
                            const float* __restrict__ Wn2, const float* __restrict__ bn2,
                            const float* __restrict__ Ws2, const float* __restrict__ bs2,
                            const float* __restrict__ bih0, const float* __restrict__ bhh0,
                            const float* __restrict__ bih1, const float* __restrict__ bhh1) {
    const int tid = threadIdx.x;
    if (tid < 64) {
        float row[17];
        float deg = 0.0f;
#pragma unroll
        for (int k = 0; k < 17; k++) {
            int j = tid - 8 + k;
            float a = 0.0f;
            if (j >= 0 && j < 64 && j != tid) a = 1.0f / (1.0f + expf(-E[tid * 64 + j]));
            row[k] = a;
            deg += a;
        }
        float inv = deg > 0.0f ? 1.0f / deg : 0.0f;
#pragma unroll
        for (int k = 0; k < 17; k++) g_awT[k * 64 + tid] = row[k] * inv;
        g_b1[tid] = bs1[tid] + bn1[tid];
        g_b2[tid] = bs2[tid] + bn2[tid];
        g_w1[tid]       = Ws1[tid * 2 + 0];
        g_w1[64 + tid]  = Ws1[tid * 2 + 1];
        g_w1[128 + tid] = Wn1[tid * 2 + 0];
        g_w1[192 + tid] = Wn1[tid * 2 + 1];
    }
    __syncthreads();
    for (int idx = tid; idx < 17 * 64; idx += 256) {
        float v = g_awT[idx];
        g_awT2[idx * 2 + 0] = v;
        g_awT2[idx * 2 + 1] = v;
    }
    // B = [Ws2 | Wn2] split into bf16 hi/lo, padded [64][136]
    __nv_bfloat16* Bh = (__nv_bfloat16*)g_Bh4;
    __nv_bfloat16* Bl = (__nv_bfloat16*)g_Bl4;
    for (int idx = tid; idx < 64 * 136; idx += 256) {
        Bh[idx] = __float2bfloat16(0.0f);
        Bl[idx] = __float2bfloat16(0.0f);
    }
    __syncthreads();
    for (int idx = tid; idx < 64 * 128; idx += 256) {
        int o = idx >> 7, k = idx & 127;
        float w = (k < 64) ? Ws2[o * 64 + k] : Wn2[o * 64 + (k - 64)];
        __nv_bfloat16 hi = __float2bfloat16(w);
        __nv_bfloat16 lo = __float2bfloat16(w - __bfloat162float(hi));
        Bh[o * 136 + k] = hi;
        Bl[o * 136 + k] = lo;
    }
    for (int idx = tid; idx < 512; idx += 256) {
        g_b0c[idx] = bih0[idx] + bhh0[idx];
        g_b1l[idx] = bih1[idx] + bhh1[idx];
    }
}

// ---------------- prep (big transposes, multi-block) ----------------
__global__ void prep_big_kernel(const float* __restrict__ Wih0,
                                const float* __restrict__ Wc1) {
    int idx = blockIdx.x * blockDim.x + threadIdx.x;
    if (idx < 512 * 64) {
        int n = idx >> 6, k = idx & 63;
        g_Wih0t[k * 512 + n] = Wih0[idx];
    }
    if (idx < 64 * 128) {
        int o = idx >> 7, k = idx & 127;
        g_Wc1t[k * 64 + o] = Wc1[idx];
    }
}

__global__ void zero_kernel() {
    int i = blockIdx.x * blockDim.x + threadIdx.x;
    if (i < NBATCH * RHD) {
        g_H0[1][i] = 0.0f;
        g_C0[i]    = 0.0f;
        g_H1[1][i] = 0.0f;
        g_C1[i]    = 0.0f;
    }
}

// ---------------- fused GNN: 1 patch/CTA, mma.sync bf16-split, 2 CTAs/SM ----------------
// smem byte offsets (total 113664 B -> 2 CTAs/SM):
#define OFF_X1    0          // [64][64] fp32 = 16384 (reused with N1 as epilogue stage)
#define OFF_N1    16384      // 16384
#define OFF_AH    32768      // [64][136] bf16 = 17408
#define OFF_AL    50176
#define OFF_BH    67584
#define OFF_BL    84992
#define OFF_AWT2  102400     // 2176 floats = 8704
#define OFF_X0    111104
#define OFF_N0    111616
#define OFF_W1    112128
#define OFF_B1S   113152
#define OFF_B2S   113408
#define GNN_SMEM_BYTES 113664
__global__ __launch_bounds__(256, 2) void gnn_kernel(const float* __restrict__ I,
                                                     const float* __restrict__ Q) {
    extern __shared__ char smc[];
    float* const x1   = (float*)(smc + OFF_X1);
    float* const n1   = (float*)(smc + OFF_N1);
    float* const awT2 = (float*)(smc + OFF_AWT2);
    float* const x0   = (float*)(smc + OFF_X0);
    float* const n0   = (float*)(smc + OFF_N0);
    float* const w1   = (float*)(smc + OFF_W1);
    float* const b1s  = (float*)(smc + OFF_B1S);
    float* const b2s  = (float*)(smc + OFF_B2S);

    const int tid = threadIdx.x;
    const int wid = tid >> 5;
    const int lid = tid & 31;
    const unsigned sbase = smem_u32(smc);

    // B tiles + tables into smem
    for (int idx = tid; idx < 1088; idx += 256) {
        ((uint4*)(smc + OFF_BH))[idx] = g_Bh4[idx];
        ((uint4*)(smc + OFF_BL))[idx] = g_Bl4[idx];
    }
    for (int idx = tid; idx < 2176; idx += 256) awT2[idx] = g_awT2[idx];
    w1[tid] = g_w1[tid];
    if (tid < 64) {
        b1s[tid] = g_b1[tid];
        b2s[tid] = g_b2[tid];
    }

    const int gp = blockIdx.x;
    const int b  = gp / NP;
    const int p  = gp - b * NP;

    __syncthreads();
    if (tid < 64) {
        int pos = b * 1024 + p * 32 + tid;
        x0[tid * 2 + 0] = I[pos];
        x0[tid * 2 + 1] = Q[pos];
    }
    __syncthreads();

    // neigh0
    if (tid < 128) {
        int i = tid >> 1, dd = tid & 1;
        float s = 0.0f;
#pragma unroll
        for (int k = 0; k < 17; k++) {
            int j = i - 8 + k;
            j = max(0, min(63, j));
            s += awT2[(k * 64 + i) * 2] * x0[j * 2 + dd];
        }
        n0[tid] = s;
    }
    __syncthreads();

    // SAGE layer 1
    {
        const int o = tid & 63, ig = tid >> 6;
        const float ws0 = w1[o], ws1 = w1[64 + o], wn0 = w1[128 + o], wn1 = w1[192 + o];
        const float bb = b1s[o];
#pragma unroll
        for (int ii = 0; ii < 16; ii++) {
            int i = ig * 16 + ii;
            float v = bb + x0[i * 2] * ws0 + x0[i * 2 + 1] * ws1
                         + n0[i * 2] * wn0 + n0[i * 2 + 1] * wn1;
            x1[i * 64 + o] = fmaxf(v, 0.0f);
        }
    }
    __syncthreads();

    // banded conv -> n1 (f32x2, sliding register window)
    {
        const int dp = tid & 31;
        const int ig = tid >> 5;
        const int i0 = ig * 8;
        ull xw[24];
#pragma unroll
        for (int w = 0; w < 24; w++) {
            int j = i0 - 8 + w;
            j = max(0, min(63, j));
            xw[w] = *(const ull*)(x1 + j * 64 + 2 * dp);
        }
        ull acc[8];
#pragma unroll
        for (int ii = 0; ii < 8; ii++) acc[ii] = 0ull;
#pragma unroll
        for (int k = 0; k < 17; k++) {
#pragma unroll
            for (int ii = 0; ii < 8; ii += 2) {
                const ulonglong2 aw = *(const ulonglong2*)(awT2 + (k * 64 + i0 + ii) * 2);
                ffma2(acc[ii],     aw.x, xw[ii + k]);
                ffma2(acc[ii + 1], aw.y, xw[ii + 1 + k]);
            }
        }
#pragma unroll
        for (int ii = 0; ii < 8; ii++)
            *(ull*)(n1 + (i0 + ii) * 64 + 2 * dp) = acc[ii];
    }
    __syncthreads();

    // convert x1/n1 fp32 -> Ah/Al bf16 [64][136] (row m = node, K=128 = [x1|n1])
    {
        unsigned* Ah32 = (unsigned*)(smc + OFF_AH);
        unsigned* Al32 = (unsigned*)(smc + OFF_AL);
        for (int idx = tid; idx < 64 * 64; idx += 256) {
            const int m = idx >> 6, kp = idx & 63;   // k pair = {2kp, 2kp+1}
            const float* src = (kp < 32) ? x1 : n1;
            const float2 v = *(const float2*)(src + m * 64 + (kp & 31) * 2);
            const float h0 = __bfloat162float(__float2bfloat16(v.x));
            const float h1 = __bfloat162float(__float2bfloat16(v.y));
            const int u32i = m * 68 + kp;            // (m*136 + kp*2)/2
            Ah32[u32i] = pack_bf16x2(v.x, v.y);
            Al32[u32i] = pack_bf16x2(v.x - h0, v.y - h1);
        }
    }
    __syncthreads();

    // mma.sync GEMM: D[64x64] = Ah*B^T(h) + Ah*B^T(l) + Al*B^T(h)
    // 8 warps = 4 m-tiles (16 rows) x 2 n-halves (32 cols)
    float* stage = (float*)smc;   // x1/n1 region dead: [64][65] stage (16640 B <= 32768)
    {
        const int mt = wid & 3, nh = wid >> 2;
        const int m0 = mt * 16;
        const unsigned rA = (unsigned)(m0 + (lid & 7) + ((lid >> 3) & 1) * 8);
        const unsigned cA = (unsigned)((lid >> 4) * 8);
        unsigned aAddr = sbase + OFF_AH + (rA * 136 + cA) * 2;
        const unsigned rBp = (unsigned)(nh * 32 + (lid >> 4) * 8 + (lid & 7));
        const unsigned cBp = (unsigned)(((lid >> 3) & 1) * 8);
        unsigned bAddr = sbase + OFF_BH + (rBp * 136 + cBp) * 2;

        float acc[4][4];
#pragma unroll
        for (int nt = 0; nt < 4; nt++)
#pragma unroll
            for (int c = 0; c < 4; c++) acc[nt][c] = 0.0f;

#pragma unroll 1
        for (int ks = 0; ks < 8; ks++) {
            unsigned aH[4], aL[4], bH[8], bL[8];
            ldm4(aH, aAddr);
            ldm4(aL, aAddr + (OFF_AL - OFF_AH));
#pragma unroll
            for (int pq = 0; pq < 2; pq++) {
                ldm4(bH + 4 * pq, bAddr + pq * 4352u);
                ldm4(bL + 4 * pq, bAddr + pq * 4352u + (OFF_BL - OFF_BH));
            }
#pragma unroll
            for (int nt = 0; nt < 4; nt++) {
                mma_bf16(acc[nt], aH, bH + nt * 2);
                mma_bf16(acc[nt], aH, bL + nt * 2);
                mma_bf16(acc[nt], aL, bH + nt * 2);
            }
            aAddr += 32;
            bAddr += 32;
        }

        // epilogue: bias + relu into stage[m][o], pitch 65
        const int r = lid >> 2, cp = (lid & 3) * 2;
#pragma unroll
        for (int nt = 0; nt < 4; nt++) {
            const int o = nh * 32 + nt * 8 + cp;
            const float bb0 = b2s[o], bb1 = b2s[o + 1];
            stage[(m0 + r) * 65 + o]         = fmaxf(acc[nt][0] + bb0, 0.0f);
            stage[(m0 + r) * 65 + o + 1]     = fmaxf(acc[nt][1] + bb1, 0.0f);
            stage[(m0 + 8 + r) * 65 + o]     = fmaxf(acc[nt][2] + bb0, 0.0f);
            stage[(m0 + 8 + r) * 65 + o + 1] = fmaxf(acc[nt][3] + bb1, 0.0f);
        }
    }
    __syncthreads();
    if (tid < 64) {
        float s = 0.0f;
#pragma unroll
        for (int i = 0; i < 64; i++) s += stage[i * 65 + tid];
        g_feats[gp * 64 + tid] = s;
    }
}

// ---------------- xg0 = feats @ Wih0^T + bias : [31744 x 512], K=64 ----------------
__global__ __launch_bounds__(256) void xg0_kernel() {
    __shared__ float As[64 * 64];
    __shared__ float Bs[64 * 64];
    __shared__ float bsm[64];
    const int m0 = blockIdx.x * 64;
    const int n0 = blockIdx.y * 64;
    const int tid = threadIdx.x;
    for (int idx = tid; idx < 1024; idx += 256)
        ((float4*)As)[idx] = *(const float4*)(g_feats + (m0 + (idx >> 4)) * 64 + (idx & 15) * 4);
    for (int idx = tid; idx < 1024; idx += 256)
        ((float4*)Bs)[idx] = *(const float4*)(g_Wih0t + (idx >> 4) * 512 + n0 + (idx & 15) * 4);
    if (tid < 64) bsm[tid] = g_b0c[n0 + tid];
    __syncthreads();
    const int mi0 = (tid >> 4) * 4;
    const int ni0 = (tid & 15) * 4;
    ull acc[4][2];
#pragma unroll
    for (int ii = 0; ii < 4; ii++) { acc[ii][0] = 0ull; acc[ii][1] = 0ull; }
#pragma unroll 2
    for (int k = 0; k < 64; k += 4) {
        ulonglong2 bv[4];
#pragma unroll
        for (int kk = 0; kk < 4; kk++) bv[kk] = *(const ulonglong2*)(Bs + (k + kk) * 64 + ni0);
#pragma unroll
        for (int ii = 0; ii < 4; ii++) {
            const float4 a = *(const float4*)(As + (mi0 + ii) * 64 + k);
            ull p;
            asm("mov.b64 %0, {%1,%1};" : "=l"(p) : "f"(a.x));
            ffma2(acc[ii][0], p, bv[0].x); ffma2(acc[ii][1], p, bv[0].y);
            asm("mov.b64 %0, {%1,%1};" : "=l"(p) : "f"(a.y));
            ffma2(acc[ii][0], p, bv[1].x); ffma2(acc[ii][1], p, bv[1].y);
            asm("mov.b64 %0, {%1,%1};" : "=l"(p) : "f"(a.z));
            ffma2(acc[ii][0], p, bv[2].x); ffma2(acc[ii][1], p, bv[2].y);
            asm("mov.b64 %0, {%1,%1};" : "=l"(p) : "f"(a.w));
            ffma2(acc[ii][0], p, bv[3].x); ffma2(acc[ii][1], p, bv[3].y);
        }
    }
#pragma unroll
    for (int ii = 0; ii < 4; ii++) {
        float2 v01 = unpack2(acc[ii][0]);
        float2 v23 = unpack2(acc[ii][1]);
        float* dst = g_xg0 + (m0 + mi0 + ii) * 512 + n0 + ni0;
        dst[0] = v01.x + bsm[ni0 + 0];
        dst[1] = v01.y + bsm[ni0 + 1];
        dst[2] = v23.x + bsm[ni0 + 2];
        dst[3] = v23.y + bsm[ni0 + 3];
    }
}

// ---------------- pipelined LSTM step (R8 config) ----------------
#define LSTM_SMEM_FLOATS 24704
__global__ __launch_bounds__(256) void lstm_step_kernel(int t,
                                                        const float* __restrict__ Whh0,
                                                        const float* __restrict__ Wih1,
                                                        const float* __restrict__ Whh1) {
    extern __shared__ float sm[];
    const int tid = threadIdx.x;
    const int jj = tid & 31;
    const int bg = tid >> 5;

    if (blockIdx.x < 64) {
        if (t > 30) return;
        const int b0 = (blockIdx.x >> 2) * 64;
        const int j0 = (blockIdx.x & 3) * 32;
        float* Wp = sm;
        float* hs = sm + 16512;
        const float* __restrict__ hprev = g_H0[(t + 1) & 1];
        for (int idx = tid; idx < 2048; idx += 256)
            ((float4*)hs)[idx] = *(const float4*)(hprev + b0 * 128 + idx * 4);
        for (int idx = tid; idx < 128 * 128; idx += 256) {
            int k = idx & 127, r = idx >> 7;
            int q = r >> 5, j = r & 31;
            Wp[(k >> 1) * 258 + r * 2 + (k & 1)] = Whh0[(q * 128 + j0 + j) * 128 + k];
        }
        __syncthreads();
        ull acc[8][4];
#pragma unroll
        for (int i = 0; i < 8; i++)
#pragma unroll
            for (int q = 0; q < 4; q++) acc[i][q] = 0ull;
#pragma unroll 2
        for (int kp = 0; kp < 64; kp++) {
            const float* wrow = Wp + kp * 258 + jj * 2;
            const ull w0 = *(const ull*)(wrow);
            const ull w1v = *(const ull*)(wrow + 64);
            const ull w2 = *(const ull*)(wrow + 128);
            const ull w3 = *(const ull*)(wrow + 192);
#pragma unroll
            for (int i = 0; i < 8; i++) {
                const ull h = *(const ull*)(hs + (bg * 8 + i) * 128 + kp * 2);
                ffma2(acc[i][0], h, w0);
                ffma2(acc[i][1], h, w1v);
                ffma2(acc[i][2], h, w2);
                ffma2(acc[i][3], h, w3);
            }
        }
        const int j = j0 + jj;
#pragma unroll
        for (int i = 0; i < 8; i++) {
            int b = b0 + bg * 8 + i;
            const float* xg = g_xg0 + (b * NP + t) * 512;
            float2 s0 = unpack2(acc[i][0]);
            float2 s1 = unpack2(acc[i][1]);
            float2 s2 = unpack2(acc[i][2]);
            float2 s3 = unpack2(acc[i][3]);
            float gi = s0.x + s0.y + xg[j];
            float gf = s1.x + s1.y + xg[128 + j];
            float gg = s2.x + s2.y + xg[256 + j];
            float go = s3.x + s3.y + xg[384 + j];
            float c = g_C0[b * 128 + j];
            c = sigm(gf) * c + sigm(gi) * tanhf(gg);
            float h = sigm(go) * tanhf(c);
            g_C0[b * 128 + j] = c;
            g_H0[t & 1][b * 128 + j] = h;
        }
    } else {
        const int s = t - 1;
        if (s < 0) return;
        const int blk = blockIdx.x - 64;
        const int b0 = (blk >> 2) * 32;
        const int j0 = (blk & 3) * 32;
        float* Wp  = sm;
        float* h0s = sm + 16512;
        float* h1s = h0s + 4096;
        const float* __restrict__ h0in = g_H0[s & 1];
        const float* __restrict__ h1in = g_H1[(s & 1) ^ 1];
        for (int idx = tid; idx < 1024; idx += 256) {
            ((float4*)h0s)[idx] = *(const float4*)(h0in + b0 * 128 + idx * 4);
            ((float4*)h1s)[idx] = *(const float4*)(h1in + b0 * 128 + idx * 4);
        }
        for (int idx = tid; idx < 128 * 128; idx += 256) {
            int k = idx & 127, r = idx >> 7;
            int q = r >> 5, j = r & 31;
            Wp[(k >> 1) * 258 + r * 2 + (k & 1)] = Wih1[(q * 128 + j0 + j) * 128 + k];
        }
        __syncthreads();
        ull acc[4][4];
#pragma unroll
        for (int i = 0; i < 4; i++)
#pragma unroll
            for (int q = 0; q < 4; q++) acc[i][q] = 0ull;
#pragma unroll 2
        for (int kp = 0; kp < 64; kp++) {
            const float* wrow = Wp + kp * 258 + jj * 2;
            const ull w0 = *(const ull*)(wrow);
            const ull w1v = *(const ull*)(wrow + 64);
            const ull w2 = *(const ull*)(wrow + 128);
            const ull w3 = *(const ull*)(wrow + 192);
#pragma unroll
            for (int i = 0; i < 4; i++) {
                const ull h = *(const ull*)(h0s + (bg * 4 + i) * 128 + kp * 2);
                ffma2(acc[i][0], h, w0);
                ffma2(acc[i][1], h, w1v);
                ffma2(acc[i][2], h, w2);
                ffma2(acc[i][3], h, w3);
            }
        }
        __syncthreads();
        for (int idx = tid; idx < 128 * 128; idx += 256) {
            int k = idx & 127, r = idx >> 7;
            int q = r >> 5, j = r & 31;
            Wp[(k >> 1) * 258 + r * 2 + (k & 1)] = Whh1[(q * 128 + j0 + j) * 128 + k];
        }
        __syncthreads();
#pragma unroll 2
        for (int kp = 0; kp < 64; kp++) {
            const float* wrow = Wp + kp * 258 + jj * 2;
            const ull w0 = *(const ull*)(wrow);
            const ull w1v = *(const ull*)(wrow + 64);
            const ull w2 = *(const ull*)(wrow + 128);
            const ull w3 = *(const ull*)(wrow + 192);
#pragma unroll
            for (int i = 0; i < 4; i++) {
                const ull h = *(const ull*)(h1s + (bg * 4 + i) * 128 + kp * 2);
                ffma2(acc[i][0], h, w0);
                ffma2(acc[i][1], h, w1v);
                ffma2(acc[i][2], h, w2);
                ffma2(acc[i][3], h, w3);
            }
        }
        const int j = j0 + jj;
#pragma unroll
        for (int i = 0; i < 4; i++) {
            int b = b0 + bg * 4 + i;
            float2 s0 = unpack2(acc[i][0]);
            float2 s1 = unpack2(acc[i][1]);
            float2 s2 = unpack2(acc[i][2]);
            float2 s3 = unpack2(acc[i][3]);
            float gi = s0.x + s0.y + g_b1l[j];
            float gf = s1.x + s1.y + g_b1l[128 + j];
            float gg = s2.x + s2.y + g_b1l[256 + j];
            float go = s3.x + s3.y + g_b1l[384 + j];
            float c = g_C1[b * 128 + j];
            c = sigm(gf) * c + sigm(gi) * tanhf(gg);
            float h = sigm(go) * tanhf(c);
            g_C1[b * 128 + j] = c;
            g_H1[s & 1][b * 128 + j] = h;
        }
    }
}

// ---------------- classifier ----------------
__global__ __launch_bounds__(256) void fc1_kernel(const float* __restrict__ bc1) {
    __shared__ float w[128 * 64];
    __shared__ float hsm[4 * 128];
    __shared__ float bsm[64];
    const int tid = threadIdx.x;
    const int b0 = blockIdx.x * 4;
    for (int idx = tid; idx < 8192; idx += 256) w[idx] = g_Wc1t[idx];
    if (tid < 64) bsm[tid] = bc1[tid];
    for (int idx = tid; idx < 512; idx += 256) hsm[idx] = g_H1[0][b0 * 128 + idx];
    __syncthreads();
    const int o = tid & 63, bb = tid >> 6;
    float s = bsm[o];
#pragma unroll 8
    for (int k = 0; k < 128; k++) s += hsm[bb * 128 + k] * w[k * 64 + o];
    g_hid[(b0 + bb) * 64 + o] = fmaxf(s, 0.0f);
}

__global__ __launch_bounds__(256) void fc2_kernel(const float* __restrict__ Wc2,
                                                  const float* __restrict__ bc2,
                                                  float* __restrict__ out) {
    __shared__ float w[11 * 64];
    __shared__ float bsm[11];
    __shared__ float hs[16 * 64];
    const int tid = threadIdx.x;
    const int b0 = blockIdx.x * 16;
    for (int idx = tid; idx < 704; idx += 256) w[idx] = Wc2[idx];
    if (tid < 11) bsm[tid] = bc2[tid];
    for (int idx = tid; idx < 1024; idx += 256) hs[idx] = g_hid[b0 * 64 + idx];
    __syncthreads();
    if (tid < 176) {
        int bb = tid / 11, c = tid - bb * 11;
        float s = bsm[c];
#pragma unroll 8
        for (int k = 0; k < 64; k++) s += hs[bb * 64 + k] * w[c * 64 + k];
        out[(b0 + bb) * 11 + c] = s;
    }
}

// ---------------- launch ----------------
extern "C" void kernel_launch(void* const* d_in, const int* in_sizes, int n_in,
                              void* d_out, int out_size) {
    const float* I    = (const float*)d_in[0];
    const float* Q    = (const float*)d_in[1];
    const float* E    = (const float*)d_in[2];
    const float* Wn1  = (const float*)d_in[3];
    const float* bn1  = (const float*)d_in[4];
    const float* Ws1  = (const float*)d_in[5];
    const float* bs1  = (const float*)d_in[6];
    const float* Wn2  = (const float*)d_in[7];
    const float* bn2  = (const float*)d_in[8];
    const float* Ws2  = (const float*)d_in[9];
    const float* bs2  = (const float*)d_in[10];
    const float* Wih0 = (const float*)d_in[11];
    const float* Whh0 = (const float*)d_in[12];
    const float* bih0 = (const float*)d_in[13];
    const float* bhh0 = (const float*)d_in[14];
    const float* Wih1 = (const float*)d_in[15];
    const float* Whh1 = (const float*)d_in[16];
    const float* bih1 = (const float*)d_in[17];
    const float* bhh1 = (const float*)d_in[18];
    const float* Wc1  = (const float*)d_in[19];
    const float* bc1  = (const float*)d_in[20];
    const float* Wc2  = (const float*)d_in[21];
    const float* bc2  = (const float*)d_in[22];
    float* out = (float*)d_out;

    const size_t lstm_smem = LSTM_SMEM_FLOATS * sizeof(float);  // 98816 B
    cudaFuncSetAttribute(gnn_kernel, cudaFuncAttributeMaxDynamicSharedMemorySize, GNN_SMEM_BYTES);
    cudaFuncSetAttribute(lstm_step_kernel, cudaFuncAttributeMaxDynamicSharedMemorySize, (int)lstm_smem);

    // launch order chosen so gnn_kernel lands in the ncu capture slot (4th launch)
    prep_kernel<<<1, 256>>>(E, Wn1, bn1, Ws1, bs1, Wn2, bn2, Ws2, bs2,
                            bih0, bhh0, bih1, bhh1);
    prep_big_kernel<<<128, 256>>>(Wih0, Wc1);
    zero_kernel<<<512, 256>>>();
    gnn_kernel<<<NBATCH * NP, 256, GNN_SMEM_BYTES>>>(I, Q);
    xg0_kernel<<<dim3((NBATCH * NP) / 64, 8), 256>>>();
    for (int t = 0; t < 32; t++)
        lstm_step_kernel<<<192, 256, lstm_smem>>>(t, Whh0, Wih1, Whh1);
    fc1_kernel<<<NBATCH / 4, 256>>>(bc1);
    fc2_kernel<<<NBATCH / 16, 256>>>(Wc2, bc2, out);
    (void)in_sizes; (void)n_in; (void)out_size;
}

// round 14
// speedup vs baseline: 1.3083x; 1.1699x over previous
#include <cuda_runtime.h>
#include <cuda_bf16.h>
#include <math.h>

// ---------------- problem constants ----------------
#define NBATCH 1024
#define NP     31
#define RHD    128
#define NC     11

typedef unsigned long long ull;

// ---------------- helpers ----------------
__device__ __forceinline__ void ffma2(ull& d, ull a, ull b) {
    asm("fma.rn.f32x2 %0, %1, %2, %0;" : "+l"(d) : "l"(a), "l"(b));
}
__device__ __forceinline__ float2 unpack2(ull v) {
    float2 r; asm("mov.b64 {%0,%1}, %2;" : "=f"(r.x), "=f"(r.y) : "l"(v)); return r;
}
__device__ __forceinline__ float sigm(float x) { return 1.0f / (1.0f + expf(-x)); }
__device__ __forceinline__ unsigned smem_u32(const void* p) {
    unsigned r;
    asm("{ .reg .u64 t; cvta.to.shared.u64 t, %1; cvt.u32.u64 %0, t; }" : "=r"(r) : "l"(p));
    return r;
}
__device__ __forceinline__ void ldm4(unsigned* r, unsigned addr) {
    asm volatile("ldmatrix.sync.aligned.m8n8.x4.shared.b16 {%0,%1,%2,%3}, [%4];"
                 : "=r"(r[0]), "=r"(r[1]), "=r"(r[2]), "=r"(r[3]) : "r"(addr));
}
__device__ __forceinline__ void mma_bf16(float* c, const unsigned* a, const unsigned* b) {
    asm volatile(
        "mma.sync.aligned.m16n8k16.row.col.f32.bf16.bf16.f32 "
        "{%0,%1,%2,%3}, {%4,%5,%6,%7}, {%8,%9}, {%0,%1,%2,%3};"
        : "+f"(c[0]), "+f"(c[1]), "+f"(c[2]), "+f"(c[3])
        : "r"(a[0]), "r"(a[1]), "r"(a[2]), "r"(a[3]), "r"(b[0]), "r"(b[1]));
}
__device__ __forceinline__ unsigned pack_bf16x2(float lo, float hi) {
    unsigned short l = __bfloat16_as_ushort(__float2bfloat16(lo));
    unsigned short h = __bfloat16_as_ushort(__float2bfloat16(hi));
    return (unsigned)l | ((unsigned)h << 16);
}

// ---------------- device scratch ----------------
__device__ float g_awT[17 * 64];
__device__ float g_awT2[17 * 64 * 2];
__device__ float g_b1[64];
__device__ float g_b2[64];
__device__ float g_w1[256];
__device__ uint4 g_Bh4[1088];             // padded bf16 Bh [64][136] (17408 B)
__device__ uint4 g_Bl4[1088];             // padded bf16 Bl [64][136]
__device__ float g_b0c[512];
__device__ float g_b1l[512];
__device__ float g_Wih0t[64 * 512];
__device__ float g_Wc1t[128 * 64];
__device__ float g_feats[NBATCH * NP * 64];
__device__ float g_xg0[NBATCH * NP * 512];
__device__ float g_H0[2][NBATCH * RHD];
__device__ float g_C0[NBATCH * RHD];
__device__ float g_H1[2][NBATCH * RHD];
__device__ float g_C1[NBATCH * RHD];
__device__ float g_hid[NBATCH * 64];

// ---------------- prep (small, single block) ----------------
__global__ void prep_kernel(const float* __restrict__ E,
                            const float* __restrict__ Wn1, const float* __restrict__ bn1,
                            const float* __restrict__ Ws1, const float* __restrict__ bs1,
                            const float* __restrict__ Wn2, const float* __restrict__ bn2,
                            const float* __restrict__ Ws2, const float* __restrict__ bs2,
                            const float* __restrict__ bih0, const float* __restrict__ bhh0,
                            const float* __restrict__ bih1, const float* __restrict__ bhh1) {
    const int tid = threadIdx.x;
    if (tid < 64) {
        float row[17];
        float deg = 0.0f;
#pragma unroll
        for (int k = 0; k < 17; k++) {
            int j = tid - 8 + k;
            float a = 0.0f;
            if (j >= 0 && j < 64 && j != tid) a = 1.0f / (1.0f + expf(-E[tid * 64 + j]));
            row[k] = a;
            deg += a;
        }
        float inv = deg > 0.0f ? 1.0f / deg : 0.0f;
#pragma unroll
        for (int k = 0; k < 17; k++) g_awT[k * 64 + tid] = row[k] * inv;
        g_b1[tid] = bs1[tid] + bn1[tid];
        g_b2[tid] = bs2[tid] + bn2[tid];
        g_w1[tid]       = Ws1[tid * 2 + 0];
        g_w1[64 + tid]  = Ws1[tid * 2 + 1];
        g_w1[128 + tid] = Wn1[tid * 2 + 0];
        g_w1[192 + tid] = Wn1[tid * 2 + 1];
    }
    __syncthreads();
    for (int idx = tid; idx < 17 * 64; idx += 256) {
        float v = g_awT[idx];
        g_awT2[idx * 2 + 0] = v;
        g_awT2[idx * 2 + 1] = v;
    }
    // B = [Ws2 | Wn2] split into bf16 hi/lo, padded [64][136]
    __nv_bfloat16* Bh = (__nv_bfloat16*)g_Bh4;
    __nv_bfloat16* Bl = (__nv_bfloat16*)g_Bl4;
    for (int idx = tid; idx < 64 * 136; idx += 256) {
        Bh[idx] = __float2bfloat16(0.0f);
        Bl[idx] = __float2bfloat16(0.0f);
    }
    __syncthreads();
    for (int idx = tid; idx < 64 * 128; idx += 256) {
        int o = idx >> 7, k = idx & 127;
        float w = (k < 64) ? Ws2[o * 64 + k] : Wn2[o * 64 + (k - 64)];
        __nv_bfloat16 hi = __float2bfloat16(w);
        __nv_bfloat16 lo = __float2bfloat16(w - __bfloat162float(hi));
        Bh[o * 136 + k] = hi;
        Bl[o * 136 + k] = lo;
    }
    for (int idx = tid; idx < 512; idx += 256) {
        g_b0c[idx] = bih0[idx] + bhh0[idx];
        g_b1l[idx] = bih1[idx] + bhh1[idx];
    }
}

// ---------------- prep (big transposes, multi-block) ----------------
__global__ void prep_big_kernel(const float* __restrict__ Wih0,
                                const float* __restrict__ Wc1) {
    int idx = blockIdx.x * blockDim.x + threadIdx.x;
    if (idx < 512 * 64) {
        int n = idx >> 6, k = idx & 63;
        g_Wih0t[k * 512 + n] = Wih0[idx];
    }
    if (idx < 64 * 128) {
        int o = idx >> 7, k = idx & 127;
        g_Wc1t[k * 64 + o] = Wc1[idx];
    }
}

__global__ void zero_kernel() {
    int i = blockIdx.x * blockDim.x + threadIdx.x;
    if (i < NBATCH * RHD) {
        g_H0[1][i] = 0.0f;
        g_C0[i]    = 0.0f;
        g_H1[1][i] = 0.0f;
        g_C1[i]    = 0.0f;
    }
}

// ---------------- fused GNN: 1 patch/CTA, fused bf16 split, shfl epilogue ----------------
// smem byte offsets (total 98304 B -> 2 CTAs/SM):
#define OFF_X1    0          // [64][64] fp32 = 16384
#define OFF_AH    16384      // [64][136] bf16 = 17408
#define OFF_AL    33792
#define OFF_BH    51200
#define OFF_BL    68608
#define OFF_AWT2  86016      // 2176 floats = 8704
#define OFF_X0    94720      // 512
#define OFF_N0    95232      // 512
#define OFF_W1    95744      // 1024
#define OFF_B1S   96768      // 256
#define OFF_B2S   97024      // 256
#define OFF_PART  97280      // [4][64] fp32 = 1024
#define GNN_SMEM_BYTES 98304
__global__ __launch_bounds__(256, 2) void gnn_kernel(const float* __restrict__ I,
                                                     const float* __restrict__ Q) {
    extern __shared__ char smc[];
    float* const x1   = (float*)(smc + OFF_X1);
    float* const awT2 = (float*)(smc + OFF_AWT2);
    float* const x0   = (float*)(smc + OFF_X0);
    float* const n0   = (float*)(smc + OFF_N0);
    float* const w1   = (float*)(smc + OFF_W1);
    float* const b1s  = (float*)(smc + OFF_B1S);
    float* const b2s  = (float*)(smc + OFF_B2S);
    float* const part = (float*)(smc + OFF_PART);
    __nv_bfloat16* const Ah16 = (__nv_bfloat16*)(smc + OFF_AH);
    __nv_bfloat16* const Al16 = (__nv_bfloat16*)(smc + OFF_AL);
    unsigned* const Ah32 = (unsigned*)(smc + OFF_AH);
    unsigned* const Al32 = (unsigned*)(smc + OFF_AL);

    const int tid = threadIdx.x;
    const int wid = tid >> 5;
    const int lid = tid & 31;
    const unsigned sbase = smem_u32(smc);

    // B tiles + tables into smem
    for (int idx = tid; idx < 1088; idx += 256) {
        ((uint4*)(smc + OFF_BH))[idx] = g_Bh4[idx];
        ((uint4*)(smc + OFF_BL))[idx] = g_Bl4[idx];
    }
    for (int idx = tid; idx < 2176; idx += 256) awT2[idx] = g_awT2[idx];
    w1[tid] = g_w1[tid];
    if (tid < 64) {
        b1s[tid] = g_b1[tid];
        b2s[tid] = g_b2[tid];
    }

    const int gp = blockIdx.x;
    const int b  = gp / NP;
    const int p  = gp - b * NP;

    __syncthreads();
    if (tid < 64) {
        int pos = b * 1024 + p * 32 + tid;
        x0[tid * 2 + 0] = I[pos];
        x0[tid * 2 + 1] = Q[pos];
    }
    __syncthreads();

    // neigh0
    if (tid < 128) {
        int i = tid >> 1, dd = tid & 1;
        float s = 0.0f;
#pragma unroll
        for (int k = 0; k < 17; k++) {
            int j = i - 8 + k;
            j = max(0, min(63, j));
            s += awT2[(k * 64 + i) * 2] * x0[j * 2 + dd];
        }
        n0[tid] = s;
    }
    __syncthreads();

    // SAGE layer 1: write x1 fp32 AND Ah/Al left half (k = o)
    {
        const int o = tid & 63, ig = tid >> 6;
        const float ws0 = w1[o], ws1 = w1[64 + o], wn0 = w1[128 + o], wn1 = w1[192 + o];
        const float bb = b1s[o];
#pragma unroll
        for (int ii = 0; ii < 16; ii++) {
            int i = ig * 16 + ii;
            float v = bb + x0[i * 2] * ws0 + x0[i * 2 + 1] * ws1
                         + n0[i * 2] * wn0 + n0[i * 2 + 1] * wn1;
            v = fmaxf(v, 0.0f);
            x1[i * 64 + o] = v;
            __nv_bfloat16 hi = __float2bfloat16(v);
            Ah16[i * 136 + o] = hi;
            Al16[i * 136 + o] = __float2bfloat16(v - __bfloat162float(hi));
        }
    }
    __syncthreads();

    // banded conv -> Ah/Al right half (k = 64 + 2dp, 64 + 2dp + 1), f32x2 sliding window
    {
        const int dp = tid & 31;
        const int ig = tid >> 5;
        const int i0 = ig * 8;
        ull xw[24];
#pragma unroll
        for (int w = 0; w < 24; w++) {
            int j = i0 - 8 + w;
            j = max(0, min(63, j));
            xw[w] = *(const ull*)(x1 + j * 64 + 2 * dp);
        }
        ull acc[8];
#pragma unroll
        for (int ii = 0; ii < 8; ii++) acc[ii] = 0ull;
#pragma unroll
        for (int k = 0; k < 17; k++) {
#pragma unroll
            for (int ii = 0; ii < 8; ii += 2) {
                const ulonglong2 aw = *(const ulonglong2*)(awT2 + (k * 64 + i0 + ii) * 2);
                ffma2(acc[ii],     aw.x, xw[ii + k]);
                ffma2(acc[ii + 1], aw.y, xw[ii + 1 + k]);
            }
        }
#pragma unroll
        for (int ii = 0; ii < 8; ii++) {
            const float2 v = unpack2(acc[ii]);
            const float h0 = __bfloat162float(__float2bfloat16(v.x));
            const float h1 = __bfloat162float(__float2bfloat16(v.y));
            const int u32i = (i0 + ii) * 68 + 32 + dp;   // (m*136 + 64 + 2dp)/2
            Ah32[u32i] = pack_bf16x2(v.x, v.y);
            Al32[u32i] = pack_bf16x2(v.x - h0, v.y - h1);
        }
    }
    __syncthreads();

    // mma.sync GEMM: D[64x64] = Ah*B^T(h) + Ah*B^T(l) + Al*B^T(h)
    // 8 warps = 4 m-tiles (16 rows) x 2 n-halves (32 cols)
    {
        const int mt = wid & 3, nh = wid >> 2;
        const int m0 = mt * 16;
        const unsigned rA = (unsigned)(m0 + (lid & 7) + ((lid >> 3) & 1) * 8);
        const unsigned cA = (unsigned)((lid >> 4) * 8);
        unsigned aAddr = sbase + OFF_AH + (rA * 136 + cA) * 2;
        const unsigned rBp = (unsigned)(nh * 32 + (lid >> 4) * 8 + (lid & 7));
        const unsigned cBp = (unsigned)(((lid >> 3) & 1) * 8);
        unsigned bAddr = sbase + OFF_BH + (rBp * 136 + cBp) * 2;

        float acc[4][4];
#pragma unroll
        for (int nt = 0; nt < 4; nt++)
#pragma unroll
            for (int c = 0; c < 4; c++) acc[nt][c] = 0.0f;

#pragma unroll 1
        for (int ks = 0; ks < 8; ks++) {
            unsigned aH[4], aL[4], bH[8], bL[8];
            ldm4(aH, aAddr);
            ldm4(aL, aAddr + (OFF_AL - OFF_AH));
#pragma unroll
            for (int pq = 0; pq < 2; pq++) {
                ldm4(bH + 4 * pq, bAddr + pq * 4352u);
                ldm4(bL + 4 * pq, bAddr + pq * 4352u + (OFF_BL - OFF_BH));
            }
#pragma unroll
            for (int nt = 0; nt < 4; nt++) {
                mma_bf16(acc[nt], aH, bH + nt * 2);
                mma_bf16(acc[nt], aH, bL + nt * 2);
                mma_bf16(acc[nt], aL, bH + nt * 2);
            }
            aAddr += 32;
            bAddr += 32;
        }

        // in-register epilogue: relu(bias + acc), reduce 16 rows via shfl, write partials
        const int cp = (lid & 3) * 2;
#pragma unroll
        for (int nt = 0; nt < 4; nt++) {
            const int o = nh * 32 + nt * 8 + cp;
            const float bb0 = b2s[o], bb1 = b2s[o + 1];
            float p0 = fmaxf(acc[nt][0] + bb0, 0.0f) + fmaxf(acc[nt][2] + bb0, 0.0f);
            float p1 = fmaxf(acc[nt][1] + bb1, 0.0f) + fmaxf(acc[nt][3] + bb1, 0.0f);
            p0 += __shfl_xor_sync(0xffffffffu, p0, 4);
            p1 += __shfl_xor_sync(0xffffffffu, p1, 4);
            p0 += __shfl_xor_sync(0xffffffffu, p0, 8);
            p1 += __shfl_xor_sync(0xffffffffu, p1, 8);
            p0 += __shfl_xor_sync(0xffffffffu, p0, 16);
            p1 += __shfl_xor_sync(0xffffffffu, p1, 16);
            if (lid < 4) {
                part[mt * 64 + o]     = p0;
                part[mt * 64 + o + 1] = p1;
            }
        }
    }
    __syncthreads();
    if (tid < 64) {
        g_feats[gp * 64 + tid] = part[tid] + part[64 + tid] + part[128 + tid] + part[192 + tid];
    }
}

// ---------------- xg0 = feats @ Wih0^T + bias : [31744 x 512], K=64 ----------------
__global__ __launch_bounds__(256) void xg0_kernel() {
    __shared__ float As[64 * 64];
    __shared__ float Bs[64 * 64];
    __shared__ float bsm[64];
    const int m0 = blockIdx.x * 64;
    const int n0 = blockIdx.y * 64;
    const int tid = threadIdx.x;
    for (int idx = tid; idx < 1024; idx += 256)
        ((float4*)As)[idx] = *(const float4*)(g_feats + (m0 + (idx >> 4)) * 64 + (idx & 15) * 4);
    for (int idx = tid; idx < 1024; idx += 256)
        ((float4*)Bs)[idx] = *(const float4*)(g_Wih0t + (idx >> 4) * 512 + n0 + (idx & 15) * 4);
    if (tid < 64) bsm[tid] = g_b0c[n0 + tid];
    __syncthreads();
    const int mi0 = (tid >> 4) * 4;
    const int ni0 = (tid & 15) * 4;
    ull acc[4][2];
#pragma unroll
    for (int ii = 0; ii < 4; ii++) { acc[ii][0] = 0ull; acc[ii][1] = 0ull; }
#pragma unroll 2
    for (int k = 0; k < 64; k += 4) {
        ulonglong2 bv[4];
#pragma unroll
        for (int kk = 0; kk < 4; kk++) bv[kk] = *(const ulonglong2*)(Bs + (k + kk) * 64 + ni0);
#pragma unroll
        for (int ii = 0; ii < 4; ii++) {
            const float4 a = *(const float4*)(As + (mi0 + ii) * 64 + k);
            ull p;
            asm("mov.b64 %0, {%1,%1};" : "=l"(p) : "f"(a.x));
            ffma2(acc[ii][0], p, bv[0].x); ffma2(acc[ii][1], p, bv[0].y);
            asm("mov.b64 %0, {%1,%1};" : "=l"(p) : "f"(a.y));
            ffma2(acc[ii][0], p, bv[1].x); ffma2(acc[ii][1], p, bv[1].y);
            asm("mov.b64 %0, {%1,%1};" : "=l"(p) : "f"(a.z));
            ffma2(acc[ii][0], p, bv[2].x); ffma2(acc[ii][1], p, bv[2].y);
            asm("mov.b64 %0, {%1,%1};" : "=l"(p) : "f"(a.w));
            ffma2(acc[ii][0], p, bv[3].x); ffma2(acc[ii][1], p, bv[3].y);
        }
    }
#pragma unroll
    for (int ii = 0; ii < 4; ii++) {
        float2 v01 = unpack2(acc[ii][0]);
        float2 v23 = unpack2(acc[ii][1]);
        float* dst = g_xg0 + (m0 + mi0 + ii) * 512 + n0 + ni0;
        dst[0] = v01.x + bsm[ni0 + 0];
        dst[1] = v01.y + bsm[ni0 + 1];
        dst[2] = v23.x + bsm[ni0 + 2];
        dst[3] = v23.y + bsm[ni0 + 3];
    }
}

// ---------------- pipelined LSTM step (R8 config) ----------------
#define LSTM_SMEM_FLOATS 24704
__global__ __launch_bounds__(256) void lstm_step_kernel(int t,
                                                        const float* __restrict__ Whh0,
                                                        const float* __restrict__ Wih1,
                                                        const float* __restrict__ Whh1) {
    extern __shared__ float sm[];
    const int tid = threadIdx.x;
    const int jj = tid & 31;
    const int bg = tid >> 5;

    if (blockIdx.x < 64) {
        if (t > 30) return;
        const int b0 = (blockIdx.x >> 2) * 64;
        const int j0 = (blockIdx.x & 3) * 32;
        float* Wp = sm;
        float* hs = sm + 16512;
        const float* __restrict__ hprev = g_H0[(t + 1) & 1];
        for (int idx = tid; idx < 2048; idx += 256)
            ((float4*)hs)[idx] = *(const float4*)(hprev + b0 * 128 + idx * 4);
        for (int idx = tid; idx < 128 * 128; idx += 256) {
            int k = idx & 127, r = idx >> 7;
            int q = r >> 5, j = r & 31;
            Wp[(k >> 1) * 258 + r * 2 + (k & 1)] = Whh0[(q * 128 + j0 + j) * 128 + k];
        }
        __syncthreads();
        ull acc[8][4];
#pragma unroll
        for (int i = 0; i < 8; i++)
#pragma unroll
            for (int q = 0; q < 4; q++) acc[i][q] = 0ull;
#pragma unroll 2
        for (int kp = 0; kp < 64; kp++) {
            const float* wrow = Wp + kp * 258 + jj * 2;
            const ull w0 = *(const ull*)(wrow);
            const ull w1v = *(const ull*)(wrow + 64);
            const ull w2 = *(const ull*)(wrow + 128);
            const ull w3 = *(const ull*)(wrow + 192);
#pragma unroll
            for (int i = 0; i < 8; i++) {
                const ull h = *(const ull*)(hs + (bg * 8 + i) * 128 + kp * 2);
                ffma2(acc[i][0], h, w0);
                ffma2(acc[i][1], h, w1v);
                ffma2(acc[i][2], h, w2);
                ffma2(acc[i][3], h, w3);
            }
        }
        const int j = j0 + jj;
#pragma unroll
        for (int i = 0; i < 8; i++) {
            int b = b0 + bg * 8 + i;
            const float* xg = g_xg0 + (b * NP + t) * 512;
            float2 s0 = unpack2(acc[i][0]);
            float2 s1 = unpack2(acc[i][1]);
            float2 s2 = unpack2(acc[i][2]);
            float2 s3 = unpack2(acc[i][3]);
            float gi = s0.x + s0.y + xg[j];
            float gf = s1.x + s1.y + xg[128 + j];
            float gg = s2.x + s2.y + xg[256 + j];
            float go = s3.x + s3.y + xg[384 + j];
            float c = g_C0[b * 128 + j];
            c = sigm(gf) * c + sigm(gi) * tanhf(gg);
            float h = sigm(go) * tanhf(c);
            g_C0[b * 128 + j] = c;
            g_H0[t & 1][b * 128 + j] = h;
        }
    } else {
        const int s = t - 1;
        if (s < 0) return;
        const int blk = blockIdx.x - 64;
        const int b0 = (blk >> 2) * 32;
        const int j0 = (blk & 3) * 32;
        float* Wp  = sm;
        float* h0s = sm + 16512;
        float* h1s = h0s + 4096;
        const float* __restrict__ h0in = g_H0[s & 1];
        const float* __restrict__ h1in = g_H1[(s & 1) ^ 1];
        for (int idx = tid; idx < 1024; idx += 256) {
            ((float4*)h0s)[idx] = *(const float4*)(h0in + b0 * 128 + idx * 4);
            ((float4*)h1s)[idx] = *(const float4*)(h1in + b0 * 128 + idx * 4);
        }
        for (int idx = tid; idx < 128 * 128; idx += 256) {
            int k = idx & 127, r = idx >> 7;
            int q = r >> 5, j = r & 31;
            Wp[(k >> 1) * 258 + r * 2 + (k & 1)] = Wih1[(q * 128 + j0 + j) * 128 + k];
        }
        __syncthreads();
        ull acc[4][4];
#pragma unroll
        for (int i = 0; i < 4; i++)
#pragma unroll
            for (int q = 0; q < 4; q++) acc[i][q] = 0ull;
#pragma unroll 2
        for (int kp = 0; kp < 64; kp++) {
            const float* wrow = Wp + kp * 258 + jj * 2;
            const ull w0 = *(const ull*)(wrow);
            const ull w1v = *(const ull*)(wrow + 64);
            const ull w2 = *(const ull*)(wrow + 128);
            const ull w3 = *(const ull*)(wrow + 192);
#pragma unroll
            for (int i = 0; i < 4; i++) {
                const ull h = *(const ull*)(h0s + (bg * 4 + i) * 128 + kp * 2);
                ffma2(acc[i][0], h, w0);
                ffma2(acc[i][1], h, w1v);
                ffma2(acc[i][2], h, w2);
                ffma2(acc[i][3], h, w3);
            }
        }
        __syncthreads();
        for (int idx = tid; idx < 128 * 128; idx += 256) {
            int k = idx & 127, r = idx >> 7;
            int q = r >> 5, j = r & 31;
            Wp[(k >> 1) * 258 + r * 2 + (k & 1)] = Whh1[(q * 128 + j0 + j) * 128 + k];
        }
        __syncthreads();
#pragma unroll 2
        for (int kp = 0; kp < 64; kp++) {
            const float* wrow = Wp + kp * 258 + jj * 2;
            const ull w0 = *(const ull*)(wrow);
            const ull w1v = *(const ull*)(wrow + 64);
            const ull w2 = *(const ull*)(wrow + 128);
            const ull w3 = *(const ull*)(wrow + 192);
#pragma unroll
            for (int i = 0; i < 4; i++) {
                const ull h = *(const ull*)(h1s + (bg * 4 + i) * 128 + kp * 2);
                ffma2(acc[i][0], h, w0);
                ffma2(acc[i][1], h, w1v);
                ffma2(acc[i][2], h, w2);
                ffma2(acc[i][3], h, w3);
            }
        }
        const int j = j0 + jj;
#pragma unroll
        for (int i = 0; i < 4; i++) {
            int b = b0 + bg * 4 + i;
            float2 s0 = unpack2(acc[i][0]);
            float2 s1 = unpack2(acc[i][1]);
            float2 s2 = unpack2(acc[i][2]);
            float2 s3 = unpack2(acc[i][3]);
            float gi = s0.x + s0.y + g_b1l[j];
            float gf = s1.x + s1.y + g_b1l[128 + j];
            float gg = s2.x + s2.y + g_b1l[256 + j];
            float go = s3.x + s3.y + g_b1l[384 + j];
            float c = g_C1[b * 128 + j];
            c = sigm(gf) * c + sigm(gi) * tanhf(gg);
            float h = sigm(go) * tanhf(c);
            g_C1[b * 128 + j] = c;
            g_H1[s & 1][b * 128 + j] = h;
        }
    }
}

// ---------------- classifier ----------------
__global__ __launch_bounds__(256) void fc1_kernel(const float* __restrict__ bc1) {
    __shared__ float w[128 * 64];
    __shared__ float hsm[4 * 128];
    __shared__ float bsm[64];
    const int tid = threadIdx.x;
    const int b0 = blockIdx.x * 4;
    for (int idx = tid; idx < 8192; idx += 256) w[idx] = g_Wc1t[idx];
    if (tid < 64) bsm[tid] = bc1[tid];
    for (int idx = tid; idx < 512; idx += 256) hsm[idx] = g_H1[0][b0 * 128 + idx];
    __syncthreads();
    const int o = tid & 63, bb = tid >> 6;
    float s = bsm[o];
#pragma unroll 8
    for (int k = 0; k < 128; k++) s += hsm[bb * 128 + k] * w[k * 64 + o];
    g_hid[(b0 + bb) * 64 + o] = fmaxf(s, 0.0f);
}

__global__ __launch_bounds__(256) void fc2_kernel(const float* __restrict__ Wc2,
                                                  const float* __restrict__ bc2,
                                                  float* __restrict__ out) {
    __shared__ float w[11 * 64];
    __shared__ float bsm[11];
    __shared__ float hs[16 * 64];
    const int tid = threadIdx.x;
    const int b0 = blockIdx.x * 16;
    for (int idx = tid; idx < 704; idx += 256) w[idx] = Wc2[idx];
    if (tid < 11) bsm[tid] = bc2[tid];
    for (int idx = tid; idx < 1024; idx += 256) hs[idx] = g_hid[b0 * 64 + idx];
    __syncthreads();
    if (tid < 176) {
        int bb = tid / 11, c = tid - bb * 11;
        float s = bsm[c];
#pragma unroll 8
        for (int k = 0; k < 64; k++) s += hs[bb * 64 + k] * w[c * 64 + k];
        out[(b0 + bb) * 11 + c] = s;
    }
}

// ---------------- launch ----------------
extern "C" void kernel_launch(void* const* d_in, const int* in_sizes, int n_in,
                              void* d_out, int out_size) {
    const float* I    = (const float*)d_in[0];
    const float* Q    = (const float*)d_in[1];
    const float* E    = (const float*)d_in[2];
    const float* Wn1  = (const float*)d_in[3];
    const float* bn1  = (const float*)d_in[4];
    const float* Ws1  = (const float*)d_in[5];
    const float* bs1  = (const float*)d_in[6];
    const float* Wn2  = (const float*)d_in[7];
    const float* bn2  = (const float*)d_in[8];
    const float* Ws2  = (const float*)d_in[9];
    const float* bs2  = (const float*)d_in[10];
    const float* Wih0 = (const float*)d_in[11];
    const float* Whh0 = (const float*)d_in[12];
    const float* bih0 = (const float*)d_in[13];
    const float* bhh0 = (const float*)d_in[14];
    const float* Wih1 = (const float*)d_in[15];
    const float* Whh1 = (const float*)d_in[16];
    const float* bih1 = (const float*)d_in[17];
    const float* bhh1 = (const float*)d_in[18];
    const float* Wc1  = (const float*)d_in[19];
    const float* bc1  = (const float*)d_in[20];
    const float* Wc2  = (const float*)d_in[21];
    const float* bc2  = (const float*)d_in[22];
    float* out = (float*)d_out;

    const size_t lstm_smem = LSTM_SMEM_FLOATS * sizeof(float);  // 98816 B
    cudaFuncSetAttribute(gnn_kernel, cudaFuncAttributeMaxDynamicSharedMemorySize, GNN_SMEM_BYTES);
    cudaFuncSetAttribute(lstm_step_kernel, cudaFuncAttributeMaxDynamicSharedMemorySize, (int)lstm_smem);

    // launch order chosen so gnn_kernel lands in the ncu capture slot (4th launch)
    prep_kernel<<<1, 256>>>(E, Wn1, bn1, Ws1, bs1, Wn2, bn2, Ws2, bs2,
                            bih0, bhh0, bih1, bhh1);
    prep_big_kernel<<<128, 256>>>(Wih0, Wc1);
    zero_kernel<<<512, 256>>>();
    gnn_kernel<<<NBATCH * NP, 256, GNN_SMEM_BYTES>>>(I, Q);
    xg0_kernel<<<dim3((NBATCH * NP) / 64, 8), 256>>>();
    for (int t = 0; t < 32; t++)
        lstm_step_kernel<<<192, 256, lstm_smem>>>(t, Whh0, Wih1, Whh1);
    fc1_kernel<<<NBATCH / 4, 256>>>(bc1);
    fc2_kernel<<<NBATCH / 16, 256>>>(Wc2, bc2, out);
    (void)in_sizes; (void)n_in; (void)out_size;
}

// round 16
// speedup vs baseline: 1.3375x; 1.0223x over previous
#include <cuda_runtime.h>
#include <cuda_bf16.h>
#include <math.h>

// ---------------- problem constants ----------------
#define NBATCH 1024
#define NP     31
#define RHD    128
#define NC     11

typedef unsigned long long ull;

// ---------------- helpers ----------------
__device__ __forceinline__ void ffma2(ull& d, ull a, ull b) {
    asm("fma.rn.f32x2 %0, %1, %2, %0;" : "+l"(d) : "l"(a), "l"(b));
}
__device__ __forceinline__ float2 unpack2(ull v) {
    float2 r; asm("mov.b64 {%0,%1}, %2;" : "=f"(r.x), "=f"(r.y) : "l"(v)); return r;
}
__device__ __forceinline__ float sigm(float x) { return 1.0f / (1.0f + expf(-x)); }
__device__ __forceinline__ unsigned smem_u32(const void* p) {
    unsigned r;
    asm("{ .reg .u64 t; cvta.to.shared.u64 t, %1; cvt.u32.u64 %0, t; }" : "=r"(r) : "l"(p));
    return r;
}
__device__ __forceinline__ void ldm4(unsigned* r, unsigned addr) {
    asm volatile("ldmatrix.sync.aligned.m8n8.x4.shared.b16 {%0,%1,%2,%3}, [%4];"
                 : "=r"(r[0]), "=r"(r[1]), "=r"(r[2]), "=r"(r[3]) : "r"(addr));
}
__device__ __forceinline__ void mma_bf16(float* c, const unsigned* a, const unsigned* b) {
    asm volatile(
        "mma.sync.aligned.m16n8k16.row.col.f32.bf16.bf16.f32 "
        "{%0,%1,%2,%3}, {%4,%5,%6,%7}, {%8,%9}, {%0,%1,%2,%3};"
        : "+f"(c[0]), "+f"(c[1]), "+f"(c[2]), "+f"(c[3])
        : "r"(a[0]), "r"(a[1]), "r"(a[2]), "r"(a[3]), "r"(b[0]), "r"(b[1]));
}
__device__ __forceinline__ unsigned pack_bf16x2(float lo, float hi) {
    unsigned short l = __bfloat16_as_ushort(__float2bfloat16(lo));
    unsigned short h = __bfloat16_as_ushort(__float2bfloat16(hi));
    return (unsigned)l | ((unsigned)h << 16);
}

// ---------------- device scratch ----------------
__device__ float g_awT[17 * 64];
__device__ float g_awT2[17 * 64 * 2];
__device__ float g_b1[64];
__device__ float g_b2[64];
__device__ float g_w1[256];
__device__ uint4 g_Bh4[1088];             // padded bf16 Bh [64][136] (17408 B)
__device__ uint4 g_Bl4[1088];             // padded bf16 Bl [64][136]
__device__ float g_b0c[512];
__device__ float g_b1l[512];
__device__ float g_Wih0t[64 * 512];
__device__ float g_Wc1t[128 * 64];
__device__ float g_Wp0[4 * 16640];        // packed Whh0 per j0-tile, pitch 260
__device__ float g_Wp1i[4 * 16640];       // packed Wih1
__device__ float g_Wp1h[4 * 16640];       // packed Whh1
__device__ float g_feats[NBATCH * NP * 64];
__device__ float g_xg0[NBATCH * NP * 512];
__device__ float g_H0[2][NBATCH * RHD];
__device__ float g_C0[NBATCH * RHD];
__device__ float g_H1[2][NBATCH * RHD];
__device__ float g_C1[NBATCH * RHD];
__device__ float g_hid[NBATCH * 64];

// ---------------- prep (small, single block) ----------------
__global__ void prep_kernel(const float* __restrict__ E,
                            const float* __restrict__ Wn1, const float* __restrict__ bn1,
                            const float* __restrict__ Ws1, const float* __restrict__ bs1,
                            const float* __restrict__ Wn2, const float* __restrict__ bn2,
                            const float* __restrict__ Ws2, const float* __restrict__ bs2,
                            const float* __restrict__ bih0, const float* __restrict__ bhh0,
                            const float* __restrict__ bih1, const float* __restrict__ bhh1) {
    const int tid = threadIdx.x;
    if (tid < 64) {
        float row[17];
        float deg = 0.0f;
#pragma unroll
        for (int k = 0; k < 17; k++) {
            int j = tid - 8 + k;
            float a = 0.0f;
            if (j >= 0 && j < 64 && j != tid) a = 1.0f / (1.0f + expf(-E[tid * 64 + j]));
            row[k] = a;
            deg += a;
        }
        float inv = deg > 0.0f ? 1.0f / deg : 0.0f;
#pragma unroll
        for (int k = 0; k < 17; k++) g_awT[k * 64 + tid] = row[k] * inv;
        g_b1[tid] = bs1[tid] + bn1[tid];
        g_b2[tid] = bs2[tid] + bn2[tid];
        g_w1[tid]       = Ws1[tid * 2 + 0];
        g_w1[64 + tid]  = Ws1[tid * 2 + 1];
        g_w1[128 + tid] = Wn1[tid * 2 + 0];
        g_w1[192 + tid] = Wn1[tid * 2 + 1];
    }
    __syncthreads();
    for (int idx = tid; idx < 17 * 64; idx += 256) {
        float v = g_awT[idx];
        g_awT2[idx * 2 + 0] = v;
        g_awT2[idx * 2 + 1] = v;
    }
    // B = [Ws2 | Wn2] split into bf16 hi/lo, padded [64][136]
    __nv_bfloat16* Bh = (__nv_bfloat16*)g_Bh4;
    __nv_bfloat16* Bl = (__nv_bfloat16*)g_Bl4;
    for (int idx = tid; idx < 64 * 136; idx += 256) {
        Bh[idx] = __float2bfloat16(0.0f);
        Bl[idx] = __float2bfloat16(0.0f);
    }
    __syncthreads();
    for (int idx = tid; idx < 64 * 128; idx += 256) {
        int o = idx >> 7, k = idx & 127;
        float w = (k < 64) ? Ws2[o * 64 + k] : Wn2[o * 64 + (k - 64)];
        __nv_bfloat16 hi = __float2bfloat16(w);
        __nv_bfloat16 lo = __float2bfloat16(w - __bfloat162float(hi));
        Bh[o * 136 + k] = hi;
        Bl[o * 136 + k] = lo;
    }
    for (int idx = tid; idx < 512; idx += 256) {
        g_b0c[idx] = bih0[idx] + bhh0[idx];
        g_b1l[idx] = bih1[idx] + bhh1[idx];
    }
}

// ---------------- prep (big transposes + LSTM weight packing) ----------------
__global__ void prep_big_kernel(const float* __restrict__ Wih0,
                                const float* __restrict__ Wc1,
                                const float* __restrict__ Whh0,
                                const float* __restrict__ Wih1,
                                const float* __restrict__ Whh1) {
    int idx = blockIdx.x * blockDim.x + threadIdx.x;   // 0..65535
    if (idx < 512 * 64) {
        int n = idx >> 6, k = idx & 63;
        g_Wih0t[k * 512 + n] = Wih0[idx];
    }
    if (idx < 64 * 128) {
        int o = idx >> 7, k = idx & 127;
        g_Wc1t[k * 64 + o] = Wc1[idx];
    }
    if (idx < 65536) {
        int R = idx >> 7, k = idx & 127;           // source row, col
        int q = R >> 7, j0t = (R >> 5) & 3, j = R & 31;
        int dst = j0t * 16640 + (k >> 1) * 260 + (q * 32 + j) * 2 + (k & 1);
        g_Wp0[dst]  = Whh0[idx];
        g_Wp1i[dst] = Wih1[idx];
        g_Wp1h[dst] = Whh1[idx];
    }
}

__global__ void zero_kernel() {
    int i = blockIdx.x * blockDim.x + threadIdx.x;
    if (i < NBATCH * RHD) {
        g_H0[1][i] = 0.0f;
        g_C0[i]    = 0.0f;
        g_H1[1][i] = 0.0f;
        g_C1[i]    = 0.0f;
    }
}

// ---------------- fused GNN: bf16 3-pass MMA, fused split, shfl epilogue ----------------
// smem byte offsets (total 98304 B -> 2 CTAs/SM):
#define OFF_X1    0          // [64][64] fp32 = 16384
#define OFF_AH    16384      // [64][136] bf16 = 17408
#define OFF_AL    33792
#define OFF_BH    51200
#define OFF_BL    68608
#define OFF_AWT2  86016      // 2176 floats = 8704
#define OFF_X0    94720
#define OFF_N0    95232
#define OFF_W1    95744
#define OFF_B1S   96768
#define OFF_B2S   97024
#define OFF_PART  97280      // [4][64] fp32 = 1024
#define GNN_SMEM_BYTES 98304
__global__ __launch_bounds__(256, 2) void gnn_kernel(const float* __restrict__ I,
                                                     const float* __restrict__ Q) {
    extern __shared__ char smc[];
    float* const x1   = (float*)(smc + OFF_X1);
    float* const awT2 = (float*)(smc + OFF_AWT2);
    float* const x0   = (float*)(smc + OFF_X0);
    float* const n0   = (float*)(smc + OFF_N0);
    float* const w1   = (float*)(smc + OFF_W1);
    float* const b1s  = (float*)(smc + OFF_B1S);
    float* const b2s  = (float*)(smc + OFF_B2S);
    float* const part = (float*)(smc + OFF_PART);
    __nv_bfloat16* const Ah16 = (__nv_bfloat16*)(smc + OFF_AH);
    __nv_bfloat16* const Al16 = (__nv_bfloat16*)(smc + OFF_AL);
    unsigned* const Ah32 = (unsigned*)(smc + OFF_AH);
    unsigned* const Al32 = (unsigned*)(smc + OFF_AL);

    const int tid = threadIdx.x;
    const int wid = tid >> 5;
    const int lid = tid & 31;
    const unsigned sbase = smem_u32(smc);

    // B tiles + tables into smem
    for (int idx = tid; idx < 1088; idx += 256) {
        ((uint4*)(smc + OFF_BH))[idx] = g_Bh4[idx];
        ((uint4*)(smc + OFF_BL))[idx] = g_Bl4[idx];
    }
    for (int idx = tid; idx < 2176; idx += 256) awT2[idx] = g_awT2[idx];
    w1[tid] = g_w1[tid];
    if (tid < 64) {
        b1s[tid] = g_b1[tid];
        b2s[tid] = g_b2[tid];
    }

    const int gp = blockIdx.x;
    const int b  = gp / NP;
    const int p  = gp - b * NP;

    __syncthreads();
    if (tid < 64) {
        int pos = b * 1024 + p * 32 + tid;
        x0[tid * 2 + 0] = I[pos];
        x0[tid * 2 + 1] = Q[pos];
    }
    __syncthreads();

    // neigh0
    if (tid < 128) {
        int i = tid >> 1, dd = tid & 1;
        float s = 0.0f;
#pragma unroll
        for (int k = 0; k < 17; k++) {
            int j = i - 8 + k;
            j = max(0, min(63, j));
            s += awT2[(k * 64 + i) * 2] * x0[j * 2 + dd];
        }
        n0[tid] = s;
    }
    __syncthreads();

    // SAGE layer 1: write x1 fp32 AND Ah/Al left half (k = o)
    {
        const int o = tid & 63, ig = tid >> 6;
        const float ws0 = w1[o], ws1 = w1[64 + o], wn0 = w1[128 + o], wn1 = w1[192 + o];
        const float bb = b1s[o];
#pragma unroll
        for (int ii = 0; ii < 16; ii++) {
            int i = ig * 16 + ii;
            float v = bb + x0[i * 2] * ws0 + x0[i * 2 + 1] * ws1
                         + n0[i * 2] * wn0 + n0[i * 2 + 1] * wn1;
            v = fmaxf(v, 0.0f);
            x1[i * 64 + o] = v;
            __nv_bfloat16 hi = __float2bfloat16(v);
            Ah16[i * 136 + o] = hi;
            Al16[i * 136 + o] = __float2bfloat16(v - __bfloat162float(hi));
        }
    }
    __syncthreads();

    // banded conv -> Ah/Al right half (k = 64 + 2dp, +1), f32x2 sliding window
    {
        const int dp = tid & 31;
        const int ig = tid >> 5;
        const int i0 = ig * 8;
        ull xw[24];
#pragma unroll
        for (int w = 0; w < 24; w++) {
            int j = i0 - 8 + w;
            j = max(0, min(63, j));
            xw[w] = *(const ull*)(x1 + j * 64 + 2 * dp);
        }
        ull acc[8];
#pragma unroll
        for (int ii = 0; ii < 8; ii++) acc[ii] = 0ull;
#pragma unroll
        for (int k = 0; k < 17; k++) {
#pragma unroll
            for (int ii = 0; ii < 8; ii += 2) {
                const ulonglong2 aw = *(const ulonglong2*)(awT2 + (k * 64 + i0 + ii) * 2);
                ffma2(acc[ii],     aw.x, xw[ii + k]);
                ffma2(acc[ii + 1], aw.y, xw[ii + 1 + k]);
            }
        }
#pragma unroll
        for (int ii = 0; ii < 8; ii++) {
            const float2 v = unpack2(acc[ii]);
            const float h0 = __bfloat162float(__float2bfloat16(v.x));
            const float h1 = __bfloat162float(__float2bfloat16(v.y));
            const int u32i = (i0 + ii) * 68 + 32 + dp;   // (m*136 + 64 + 2dp)/2
            Ah32[u32i] = pack_bf16x2(v.x, v.y);
            Al32[u32i] = pack_bf16x2(v.x - h0, v.y - h1);
        }
    }
    __syncthreads();

    // mma.sync GEMM: D[64x64] = Ah*B^T(h) + Ah*B^T(l) + Al*B^T(h)
    // 8 warps = 4 m-tiles (16 rows) x 2 n-halves (32 cols)
    {
        const int mt = wid & 3, nh = wid >> 2;
        const int m0 = mt * 16;
        const unsigned rA = (unsigned)(m0 + (lid & 7) + ((lid >> 3) & 1) * 8);
        const unsigned cA = (unsigned)((lid >> 4) * 8);
        unsigned aAddr = sbase + OFF_AH + (rA * 136 + cA) * 2;
        const unsigned rBp = (unsigned)(nh * 32 + (lid >> 4) * 8 + (lid & 7));
        const unsigned cBp = (unsigned)(((lid >> 3) & 1) * 8);
        unsigned bAddr = sbase + OFF_BH + (rBp * 136 + cBp) * 2;

        float acc[4][4];
#pragma unroll
        for (int nt = 0; nt < 4; nt++)
#pragma unroll
            for (int c = 0; c < 4; c++) acc[nt][c] = 0.0f;

#pragma unroll 1
        for (int ks = 0; ks < 8; ks++) {
            unsigned aH[4], aL[4], bH[8], bL[8];
            ldm4(aH, aAddr);
            ldm4(aL, aAddr + (OFF_AL - OFF_AH));
#pragma unroll
            for (int pq = 0; pq < 2; pq++) {
                ldm4(bH + 4 * pq, bAddr + pq * 4352u);
                ldm4(bL + 4 * pq, bAddr + pq * 4352u + (OFF_BL - OFF_BH));
            }
#pragma unroll
            for (int nt = 0; nt < 4; nt++) {
                mma_bf16(acc[nt], aH, bH + nt * 2);
                mma_bf16(acc[nt], aH, bL + nt * 2);
                mma_bf16(acc[nt], aL, bH + nt * 2);
            }
            aAddr += 32;
            bAddr += 32;
        }

        // in-register epilogue: relu(bias + acc), shfl-reduce 16 rows, write partials
        const int cp = (lid & 3) * 2;
#pragma unroll
        for (int nt = 0; nt < 4; nt++) {
            const int o = nh * 32 + nt * 8 + cp;
            const float bb0 = b2s[o], bb1 = b2s[o + 1];
            float p0 = fmaxf(acc[nt][0] + bb0, 0.0f) + fmaxf(acc[nt][2] + bb0, 0.0f);
            float p1 = fmaxf(acc[nt][1] + bb1, 0.0f) + fmaxf(acc[nt][3] + bb1, 0.0f);
            p0 += __shfl_xor_sync(0xffffffffu, p0, 4);
            p1 += __shfl_xor_sync(0xffffffffu, p1, 4);
            p0 += __shfl_xor_sync(0xffffffffu, p0, 8);
            p1 += __shfl_xor_sync(0xffffffffu, p1, 8);
            p0 += __shfl_xor_sync(0xffffffffu, p0, 16);
            p1 += __shfl_xor_sync(0xffffffffu, p1, 16);
            if (lid < 4) {
                part[mt * 64 + o]     = p0;
                part[mt * 64 + o + 1] = p1;
            }
        }
    }
    __syncthreads();
    if (tid < 64) {
        g_feats[gp * 64 + tid] = part[tid] + part[64 + tid] + part[128 + tid] + part[192 + tid];
    }
}

// ---------------- xg0 = feats @ Wih0^T + bias : [31744 x 512], K=64 ----------------
__global__ __launch_bounds__(256) void xg0_kernel() {
    __shared__ float As[64 * 64];
    __shared__ float Bs[64 * 64];
    __shared__ float bsm[64];
    const int m0 = blockIdx.x * 64;
    const int n0 = blockIdx.y * 64;
    const int tid = threadIdx.x;
    for (int idx = tid; idx < 1024; idx += 256)
        ((float4*)As)[idx] = *(const float4*)(g_feats + (m0 + (idx >> 4)) * 64 + (idx & 15) * 4);
    for (int idx = tid; idx < 1024; idx += 256)
        ((float4*)Bs)[idx] = *(const float4*)(g_Wih0t + (idx >> 4) * 512 + n0 + (idx & 15) * 4);
    if (tid < 64) bsm[tid] = g_b0c[n0 + tid];
    __syncthreads();
    const int mi0 = (tid >> 4) * 4;
    const int ni0 = (tid & 15) * 4;
    ull acc[4][2];
#pragma unroll
    for (int ii = 0; ii < 4; ii++) { acc[ii][0] = 0ull; acc[ii][1] = 0ull; }
#pragma unroll 2
    for (int k = 0; k < 64; k += 4) {
        ulonglong2 bv[4];
#pragma unroll
        for (int kk = 0; kk < 4; kk++) bv[kk] = *(const ulonglong2*)(Bs + (k + kk) * 64 + ni0);
#pragma unroll
        for (int ii = 0; ii < 4; ii++) {
            const float4 a = *(const float4*)(As + (mi0 + ii) * 64 + k);
            ull p;
            asm("mov.b64 %0, {%1,%1};" : "=l"(p) : "f"(a.x));
            ffma2(acc[ii][0], p, bv[0].x); ffma2(acc[ii][1], p, bv[0].y);
            asm("mov.b64 %0, {%1,%1};" : "=l"(p) : "f"(a.y));
            ffma2(acc[ii][0], p, bv[1].x); ffma2(acc[ii][1], p, bv[1].y);
            asm("mov.b64 %0, {%1,%1};" : "=l"(p) : "f"(a.z));
            ffma2(acc[ii][0], p, bv[2].x); ffma2(acc[ii][1], p, bv[2].y);
            asm("mov.b64 %0, {%1,%1};" : "=l"(p) : "f"(a.w));
            ffma2(acc[ii][0], p, bv[3].x); ffma2(acc[ii][1], p, bv[3].y);
        }
    }
#pragma unroll
    for (int ii = 0; ii < 4; ii++) {
        float2 v01 = unpack2(acc[ii][0]);
        float2 v23 = unpack2(acc[ii][1]);
        float* dst = g_xg0 + (m0 + mi0 + ii) * 512 + n0 + ni0;
        dst[0] = v01.x + bsm[ni0 + 0];
        dst[1] = v01.y + bsm[ni0 + 1];
        dst[2] = v23.x + bsm[ni0 + 2];
        dst[3] = v23.y + bsm[ni0 + 3];
    }
}

// ---------------- pipelined LSTM step (packed weights, pitch 260) ----------------
#define LSTM_SMEM_FLOATS 24832
__global__ __launch_bounds__(256) void lstm_step_kernel(int t) {
    extern __shared__ float sm[];
    const int tid = threadIdx.x;
    const int jj = tid & 31;
    const int bg = tid >> 5;

    if (blockIdx.x < 64) {
        if (t > 30) return;
        const int b0 = (blockIdx.x >> 2) * 64;
        const int j0 = (blockIdx.x & 3) * 32;
        float* Wp = sm;                     // 64*260
        float* hs = sm + 16640;             // [64][128]
        const float* __restrict__ hprev = g_H0[(t + 1) & 1];
        for (int idx = tid; idx < 2048; idx += 256)
            ((float4*)hs)[idx] = *(const float4*)(hprev + b0 * 128 + idx * 4);
        const float4* wsrc = (const float4*)(g_Wp0 + (blockIdx.x & 3) * 16640);
        for (int idx = tid; idx < 4160; idx += 256)
            ((float4*)Wp)[idx] = wsrc[idx];
        __syncthreads();
        ull acc[8][4];
#pragma unroll
        for (int i = 0; i < 8; i++)
#pragma unroll
            for (int q = 0; q < 4; q++) acc[i][q] = 0ull;
#pragma unroll 2
        for (int kp = 0; kp < 64; kp++) {
            const float* wrow = Wp + kp * 260 + jj * 2;
            const ull w0 = *(const ull*)(wrow);
            const ull w1v = *(const ull*)(wrow + 64);
            const ull w2 = *(const ull*)(wrow + 128);
            const ull w3 = *(const ull*)(wrow + 192);
#pragma unroll
            for (int i = 0; i < 8; i++) {
                const ull h = *(const ull*)(hs + (bg * 8 + i) * 128 + kp * 2);
                ffma2(acc[i][0], h, w0);
                ffma2(acc[i][1], h, w1v);
                ffma2(acc[i][2], h, w2);
                ffma2(acc[i][3], h, w3);
            }
        }
        const int j = j0 + jj;
#pragma unroll
        for (int i = 0; i < 8; i++) {
            int b = b0 + bg * 8 + i;
            const float* xg = g_xg0 + (b * NP + t) * 512;
            float2 s0 = unpack2(acc[i][0]);
            float2 s1 = unpack2(acc[i][1]);
            float2 s2 = unpack2(acc[i][2]);
            float2 s3 = unpack2(acc[i][3]);
            float gi = s0.x + s0.y + xg[j];
            float gf = s1.x + s1.y + xg[128 + j];
            float gg = s2.x + s2.y + xg[256 + j];
            float go = s3.x + s3.y + xg[384 + j];
            float c = g_C0[b * 128 + j];
            c = sigm(gf) * c + sigm(gi) * tanhf(gg);
            float h = sigm(go) * tanhf(c);
            g_C0[b * 128 + j] = c;
            g_H0[t & 1][b * 128 + j] = h;
        }
    } else {
        const int s = t - 1;
        if (s < 0) return;
        const int blk = blockIdx.x - 64;
        const int b0 = (blk >> 2) * 32;
        const int j0 = (blk & 3) * 32;
        float* Wp  = sm;
        float* h0s = sm + 16640;            // [32][128]
        float* h1s = h0s + 4096;            // [32][128]
        const float* __restrict__ h0in = g_H0[s & 1];
        const float* __restrict__ h1in = g_H1[(s & 1) ^ 1];
        for (int idx = tid; idx < 1024; idx += 256) {
            ((float4*)h0s)[idx] = *(const float4*)(h0in + b0 * 128 + idx * 4);
            ((float4*)h1s)[idx] = *(const float4*)(h1in + b0 * 128 + idx * 4);
        }
        const float4* wsrc1 = (const float4*)(g_Wp1i + (blk & 3) * 16640);
        for (int idx = tid; idx < 4160; idx += 256)
            ((float4*)Wp)[idx] = wsrc1[idx];
        __syncthreads();
        ull acc[4][4];
#pragma unroll
        for (int i = 0; i < 4; i++)
#pragma unroll
            for (int q = 0; q < 4; q++) acc[i][q] = 0ull;
#pragma unroll 2
        for (int kp = 0; kp < 64; kp++) {
            const float* wrow = Wp + kp * 260 + jj * 2;
            const ull w0 = *(const ull*)(wrow);
            const ull w1v = *(const ull*)(wrow + 64);
            const ull w2 = *(const ull*)(wrow + 128);
            const ull w3 = *(const ull*)(wrow + 192);
#pragma unroll
            for (int i = 0; i < 4; i++) {
                const ull h = *(const ull*)(h0s + (bg * 4 + i) * 128 + kp * 2);
                ffma2(acc[i][0], h, w0);
                ffma2(acc[i][1], h, w1v);
                ffma2(acc[i][2], h, w2);
                ffma2(acc[i][3], h, w3);
            }
        }
        __syncthreads();
        const float4* wsrc2 = (const float4*)(g_Wp1h + (blk & 3) * 16640);
        for (int idx = tid; idx < 4160; idx += 256)
            ((float4*)Wp)[idx] = wsrc2[idx];
        __syncthreads();
#pragma unroll 2
        for (int kp = 0; kp < 64; kp++) {
            const float* wrow = Wp + kp * 260 + jj * 2;
            const ull w0 = *(const ull*)(wrow);
            const ull w1v = *(const ull*)(wrow + 64);
            const ull w2 = *(const ull*)(wrow + 128);
            const ull w3 = *(const ull*)(wrow + 192);
#pragma unroll
            for (int i = 0; i < 4; i++) {
                const ull h = *(const ull*)(h1s + (bg * 4 + i) * 128 + kp * 2);
                ffma2(acc[i][0], h, w0);
                ffma2(acc[i][1], h, w1v);
                ffma2(acc[i][2], h, w2);
                ffma2(acc[i][3], h, w3);
            }
        }
        const int j = j0 + jj;
#pragma unroll
        for (int i = 0; i < 4; i++) {
            int b = b0 + bg * 4 + i;
            float2 s0 = unpack2(acc[i][0]);
            float2 s1 = unpack2(acc[i][1]);
            float2 s2 = unpack2(acc[i][2]);
            float2 s3 = unpack2(acc[i][3]);
            float gi = s0.x + s0.y + g_b1l[j];
            float gf = s1.x + s1.y + g_b1l[128 + j];
            float gg = s2.x + s2.y + g_b1l[256 + j];
            float go = s3.x + s3.y + g_b1l[384 + j];
            float c = g_C1[b * 128 + j];
            c = sigm(gf) * c + sigm(gi) * tanhf(gg);
            float h = sigm(go) * tanhf(c);
            g_C1[b * 128 + j] = c;
            g_H1[s & 1][b * 128 + j] = h;
        }
    }
}

// ---------------- classifier ----------------
__global__ __launch_bounds__(256) void fc1_kernel(const float* __restrict__ bc1) {
    __shared__ float w[128 * 64];
    __shared__ float hsm[4 * 128];
    __shared__ float bsm[64];
    const int tid = threadIdx.x;
    const int b0 = blockIdx.x * 4;
    for (int idx = tid; idx < 8192; idx += 256) w[idx] = g_Wc1t[idx];
    if (tid < 64) bsm[tid] = bc1[tid];
    for (int idx = tid; idx < 512; idx += 256) hsm[idx] = g_H1[0][b0 * 128 + idx];
    __syncthreads();
    const int o = tid & 63, bb = tid >> 6;
    float s = bsm[o];
#pragma unroll 8
    for (int k = 0; k < 128; k++) s += hsm[bb * 128 + k] * w[k * 64 + o];
    g_hid[(b0 + bb) * 64 + o] = fmaxf(s, 0.0f);
}

__global__ __launch_bounds__(256) void fc2_kernel(const float* __restrict__ Wc2,
                                                  const float* __restrict__ bc2,
                                                  float* __restrict__ out) {
    __shared__ float w[11 * 64];
    __shared__ float bsm[11];
    __shared__ float hs[16 * 64];
    const int tid = threadIdx.x;
    const int b0 = blockIdx.x * 16;
    for (int idx = tid; idx < 704; idx += 256) w[idx] = Wc2[idx];
    if (tid < 11) bsm[tid] = bc2[tid];
    for (int idx = tid; idx < 1024; idx += 256) hs[idx] = g_hid[b0 * 64 + idx];
    __syncthreads();
    if (tid < 176) {
        int bb = tid / 11, c = tid - bb * 11;
        float s = bsm[c];
#pragma unroll 8
        for (int k = 0; k < 64; k++) s += hs[bb * 64 + k] * w[c * 64 + k];
        out[(b0 + bb) * 11 + c] = s;
    }
}

// ---------------- launch ----------------
extern "C" void kernel_launch(void* const* d_in, const int* in_sizes, int n_in,
                              void* d_out, int out_size) {
    const float* I    = (const float*)d_in[0];
    const float* Q    = (const float*)d_in[1];
    const float* E    = (const float*)d_in[2];
    const float* Wn1  = (const float*)d_in[3];
    const float* bn1  = (const float*)d_in[4];
    const float* Ws1  = (const float*)d_in[5];
    const float* bs1  = (const float*)d_in[6];
    const float* Wn2  = (const float*)d_in[7];
    const float* bn2  = (const float*)d_in[8];
    const float* Ws2  = (const float*)d_in[9];
    const float* bs2  = (const float*)d_in[10];
    const float* Wih0 = (const float*)d_in[11];
    const float* Whh0 = (const float*)d_in[12];
    const float* bih0 = (const float*)d_in[13];
    const float* bhh0 = (const float*)d_in[14];
    const float* Wih1 = (const float*)d_in[15];
    const float* Whh1 = (const float*)d_in[16];
    const float* bih1 = (const float*)d_in[17];
    const float* bhh1 = (const float*)d_in[18];
    const float* Wc1  = (const float*)d_in[19];
    const float* bc1  = (const float*)d_in[20];
    const float* Wc2  = (const float*)d_in[21];
    const float* bc2  = (const float*)d_in[22];
    float* out = (float*)d_out;

    const size_t lstm_smem = LSTM_SMEM_FLOATS * sizeof(float);  // 99328 B
    cudaFuncSetAttribute(gnn_kernel, cudaFuncAttributeMaxDynamicSharedMemorySize, GNN_SMEM_BYTES);
    cudaFuncSetAttribute(lstm_step_kernel, cudaFuncAttributeMaxDynamicSharedMemorySize, (int)lstm_smem);

    // launch order chosen so gnn_kernel lands in the ncu capture slot (4th launch)
    prep_kernel<<<1, 256>>>(E, Wn1, bn1, Ws1, bs1, Wn2, bn2, Ws2, bs2,
                            bih0, bhh0, bih1, bhh1);
    prep_big_kernel<<<256, 256>>>(Wih0, Wc1, Whh0, Wih1, Whh1);
    zero_kernel<<<512, 256>>>();
    gnn_kernel<<<NBATCH * NP, 256, GNN_SMEM_BYTES>>>(I, Q);
    xg0_kernel<<<dim3((NBATCH * NP) / 64, 8), 256>>>();
    for (int t = 0; t < 32; t++)
        lstm_step_kernel<<<192, 256, lstm_smem>>>(t);
    fc1_kernel<<<NBATCH / 4, 256>>>(bc1);
    fc2_kernel<<<NBATCH / 16, 256>>>(Wc2, bc2, out);
    (void)in_sizes; (void)n_in; (void)out_size;
}

// round 17
// speedup vs baseline: 1.3746x; 1.0277x over previous
#include <cuda_runtime.h>
#include <cuda_bf16.h>
#include <math.h>

// ---------------- problem constants ----------------
#define NBATCH 1024
#define NP     31
#define RHD    128
#define NC     11

typedef unsigned long long ull;

// ---------------- helpers ----------------
__device__ __forceinline__ void ffma2(ull& d, ull a, ull b) {
    asm("fma.rn.f32x2 %0, %1, %2, %0;" : "+l"(d) : "l"(a), "l"(b));
}
__device__ __forceinline__ float2 unpack2(ull v) {
    float2 r; asm("mov.b64 {%0,%1}, %2;" : "=f"(r.x), "=f"(r.y) : "l"(v)); return r;
}
__device__ __forceinline__ float sigm(float x) { return 1.0f / (1.0f + expf(-x)); }
__device__ __forceinline__ unsigned smem_u32(const void* p) {
    unsigned r;
    asm("{ .reg .u64 t; cvta.to.shared.u64 t, %1; cvt.u32.u64 %0, t; }" : "=r"(r) : "l"(p));
    return r;
}
__device__ __forceinline__ void ldm4(unsigned* r, unsigned addr) {
    asm volatile("ldmatrix.sync.aligned.m8n8.x4.shared.b16 {%0,%1,%2,%3}, [%4];"
                 : "=r"(r[0]), "=r"(r[1]), "=r"(r[2]), "=r"(r[3]) : "r"(addr));
}
__device__ __forceinline__ void mma_bf16(float* c, const unsigned* a, const unsigned* b) {
    asm volatile(
        "mma.sync.aligned.m16n8k16.row.col.f32.bf16.bf16.f32 "
        "{%0,%1,%2,%3}, {%4,%5,%6,%7}, {%8,%9}, {%0,%1,%2,%3};"
        : "+f"(c[0]), "+f"(c[1]), "+f"(c[2]), "+f"(c[3])
        : "r"(a[0]), "r"(a[1]), "r"(a[2]), "r"(a[3]), "r"(b[0]), "r"(b[1]));
}
__device__ __forceinline__ unsigned pack_bf16x2(float lo, float hi) {
    unsigned short l = __bfloat16_as_ushort(__float2bfloat16(lo));
    unsigned short h = __bfloat16_as_ushort(__float2bfloat16(hi));
    return (unsigned)l | ((unsigned)h << 16);
}

// ---------------- device scratch ----------------
__device__ float g_awT[17 * 64];
__device__ float g_awT2[17 * 64 * 2];
__device__ float g_b1[64];
__device__ float g_b2[64];
__device__ float g_w1[256];
__device__ uint4 g_Bh4[1088];             // padded bf16 Bh [64][136] (17408 B)
__device__ uint4 g_Bl4[1088];             // padded bf16 Bl [64][136]
__device__ float g_b0c[512];
__device__ float g_b1l[512];
__device__ float g_Wih0t[64 * 512];
__device__ float g_Wc1t[128 * 64];
__device__ float g_Wp0[4 * 16640];        // packed Whh0 per j0-tile, pitch 260
__device__ float g_Wp1i[4 * 16640];       // packed Wih1
__device__ float g_Wp1h[4 * 16640];       // packed Whh1
__device__ float g_feats[NBATCH * NP * 64];
__device__ float g_xg0[NBATCH * NP * 512];
__device__ float g_H0[2][NBATCH * RHD];
__device__ float g_C0[NBATCH * RHD];
__device__ float g_H1[2][NBATCH * RHD];
__device__ float g_C1[NBATCH * RHD];
__device__ float g_hid[NBATCH * 64];

// ---------------- prep (small, single block) ----------------
__global__ void prep_kernel(const float* __restrict__ E,
                            const float* __restrict__ Wn1, const float* __restrict__ bn1,
                            const float* __restrict__ Ws1, const float* __restrict__ bs1,
                            const float* __restrict__ Wn2, const float* __restrict__ bn2,
                            const float* __restrict__ Ws2, const float* __restrict__ bs2,
                            const float* __restrict__ bih0, const float* __restrict__ bhh0,
                            const float* __restrict__ bih1, const float* __restrict__ bhh1) {
    const int tid = threadIdx.x;
    if (tid < 64) {
        float row[17];
        float deg = 0.0f;
#pragma unroll
        for (int k = 0; k < 17; k++) {
            int j = tid - 8 + k;
            float a = 0.0f;
            if (j >= 0 && j < 64 && j != tid) a = 1.0f / (1.0f + expf(-E[tid * 64 + j]));
            row[k] = a;
            deg += a;
        }
        float inv = deg > 0.0f ? 1.0f / deg : 0.0f;
#pragma unroll
        for (int k = 0; k < 17; k++) g_awT[k * 64 + tid] = row[k] * inv;
        g_b1[tid] = bs1[tid] + bn1[tid];
        g_b2[tid] = bs2[tid] + bn2[tid];
        g_w1[tid]       = Ws1[tid * 2 + 0];
        g_w1[64 + tid]  = Ws1[tid * 2 + 1];
        g_w1[128 + tid] = Wn1[tid * 2 + 0];
        g_w1[192 + tid] = Wn1[tid * 2 + 1];
    }
    __syncthreads();
    for (int idx = tid; idx < 17 * 64; idx += 256) {
        float v = g_awT[idx];
        g_awT2[idx * 2 + 0] = v;
        g_awT2[idx * 2 + 1] = v;
    }
    // B = [Ws2 | Wn2] split into bf16 hi/lo, padded [64][136]
    __nv_bfloat16* Bh = (__nv_bfloat16*)g_Bh4;
    __nv_bfloat16* Bl = (__nv_bfloat16*)g_Bl4;
    for (int idx = tid; idx < 64 * 136; idx += 256) {
        Bh[idx] = __float2bfloat16(0.0f);
        Bl[idx] = __float2bfloat16(0.0f);
    }
    __syncthreads();
    for (int idx = tid; idx < 64 * 128; idx += 256) {
        int o = idx >> 7, k = idx & 127;
        float w = (k < 64) ? Ws2[o * 64 + k] : Wn2[o * 64 + (k - 64)];
        __nv_bfloat16 hi = __float2bfloat16(w);
        __nv_bfloat16 lo = __float2bfloat16(w - __bfloat162float(hi));
        Bh[o * 136 + k] = hi;
        Bl[o * 136 + k] = lo;
    }
    for (int idx = tid; idx < 512; idx += 256) {
        g_b0c[idx] = bih0[idx] + bhh0[idx];
        g_b1l[idx] = bih1[idx] + bhh1[idx];
    }
}

// ---------------- prep (big transposes + LSTM weight packing) ----------------
__global__ void prep_big_kernel(const float* __restrict__ Wih0,
                                const float* __restrict__ Wc1,
                                const float* __restrict__ Whh0,
                                const float* __restrict__ Wih1,
                                const float* __restrict__ Whh1) {
    int idx = blockIdx.x * blockDim.x + threadIdx.x;   // 0..65535
    if (idx < 512 * 64) {
        int n = idx >> 6, k = idx & 63;
        g_Wih0t[k * 512 + n] = Wih0[idx];
    }
    if (idx < 64 * 128) {
        int o = idx >> 7, k = idx & 127;
        g_Wc1t[k * 64 + o] = Wc1[idx];
    }
    if (idx < 65536) {
        int R = idx >> 7, k = idx & 127;           // source row, col
        int q = R >> 7, j0t = (R >> 5) & 3, j = R & 31;
        int dst = j0t * 16640 + (k >> 1) * 260 + (q * 32 + j) * 2 + (k & 1);
        g_Wp0[dst]  = Whh0[idx];
        g_Wp1i[dst] = Wih1[idx];
        g_Wp1h[dst] = Whh1[idx];
    }
}

__global__ void zero_kernel() {
    int i = blockIdx.x * blockDim.x + threadIdx.x;
    if (i < NBATCH * RHD) {
        g_H0[1][i] = 0.0f;
        g_C0[i]    = 0.0f;
        g_H1[1][i] = 0.0f;
        g_C1[i]    = 0.0f;
    }
}

// ---------------- fused GNN: 2 patches/CTA, M=128 GEMM, bf16 3-pass ----------------
// smem byte offsets (total 115712 B -> 2 CTAs/SM):
#define OFF_AH    0          // [128][136] bf16 = 34816
#define OFF_AL    34816
#define OFF_BH    69632      // [64][136] bf16 = 17408
#define OFF_BL    87040
#define OFF_AWT2  104448     // 2176 floats = 8704
#define OFF_X0    113152     // 512
#define OFF_N0    113664     // 512
#define OFF_W1    114176     // 1024
#define OFF_B1S   115200     // 256
#define OFF_B2S   115456     // 256
#define OFF_PART  OFF_X0     // [2][2][64] fp32 = 1024 (aliases x0+n0, dead by epilogue)
#define GNN_SMEM_BYTES 115712
__global__ __launch_bounds__(256, 2) void gnn_kernel(const float* __restrict__ I,
                                                     const float* __restrict__ Q) {
    extern __shared__ char smc[];
    float* const awT2 = (float*)(smc + OFF_AWT2);
    float* const x0   = (float*)(smc + OFF_X0);
    float* const n0   = (float*)(smc + OFF_N0);
    float* const w1   = (float*)(smc + OFF_W1);
    float* const b1s  = (float*)(smc + OFF_B1S);
    float* const b2s  = (float*)(smc + OFF_B2S);
    float* const part = (float*)(smc + OFF_PART);
    __nv_bfloat16* const Ah16 = (__nv_bfloat16*)(smc + OFF_AH);
    __nv_bfloat16* const Al16 = (__nv_bfloat16*)(smc + OFF_AL);
    unsigned* const Ah32 = (unsigned*)(smc + OFF_AH);
    unsigned* const Al32 = (unsigned*)(smc + OFF_AL);

    const int tid = threadIdx.x;
    const int wid = tid >> 5;
    const int lid = tid & 31;
    const unsigned sbase = smem_u32(smc);

    // B tiles + tables into smem
    for (int idx = tid; idx < 1088; idx += 256) {
        ((uint4*)(smc + OFF_BH))[idx] = g_Bh4[idx];
        ((uint4*)(smc + OFF_BL))[idx] = g_Bl4[idx];
    }
    for (int idx = tid; idx < 2176; idx += 256) awT2[idx] = g_awT2[idx];
    w1[tid] = g_w1[tid];
    if (tid < 64) {
        b1s[tid] = g_b1[tid];
        b2s[tid] = g_b2[tid];
    }

    const int gp0 = blockIdx.x * 2;

    // ---- per-patch phases: x0 -> neigh0 -> sage1 -> conv ----
#pragma unroll 1
    for (int pp = 0; pp < 2; pp++) {
        const int gp = gp0 + pp;
        const int b  = gp / NP;
        const int p  = gp - b * NP;
        const int mrow = pp * 64;
        __syncthreads();
        if (tid < 64) {
            int pos = b * 1024 + p * 32 + tid;
            x0[tid * 2 + 0] = I[pos];
            x0[tid * 2 + 1] = Q[pos];
        }
        __syncthreads();

        // neigh0
        if (tid < 128) {
            int i = tid >> 1, dd = tid & 1;
            float s = 0.0f;
#pragma unroll
            for (int k = 0; k < 17; k++) {
                int j = i - 8 + k;
                j = max(0, min(63, j));
                s += awT2[(k * 64 + i) * 2] * x0[j * 2 + dd];
            }
            n0[tid] = s;
        }
        __syncthreads();

        // SAGE layer 1: write Ah/Al left half (k = o)
        {
            const int o = tid & 63, ig4 = tid >> 6;
            const float ws0 = w1[o], ws1 = w1[64 + o], wn0 = w1[128 + o], wn1 = w1[192 + o];
            const float bb = b1s[o];
#pragma unroll
            for (int ii = 0; ii < 16; ii++) {
                int i = ig4 * 16 + ii;
                float v = bb + x0[i * 2] * ws0 + x0[i * 2 + 1] * ws1
                             + n0[i * 2] * wn0 + n0[i * 2 + 1] * wn1;
                v = fmaxf(v, 0.0f);
                __nv_bfloat16 hi = __float2bfloat16(v);
                Ah16[(mrow + i) * 136 + o] = hi;
                Al16[(mrow + i) * 136 + o] = __float2bfloat16(v - __bfloat162float(hi));
            }
        }
        __syncthreads();

        // banded conv -> Ah/Al right half; input reconstructed from Ah+Al left half
        {
            const int dp = tid & 31;
            const int ig = tid >> 5;
            const int i0 = ig * 8;
            float xwx[24], xwy[24];
#pragma unroll
            for (int w = 0; w < 24; w++) {
                int j = i0 - 8 + w;
                j = max(0, min(63, j));
                const unsigned uh = Ah32[(mrow + j) * 68 + dp];
                const unsigned ul = Al32[(mrow + j) * 68 + dp];
                xwx[w] = __uint_as_float(uh << 16) + __uint_as_float(ul << 16);
                xwy[w] = __uint_as_float(uh & 0xffff0000u) + __uint_as_float(ul & 0xffff0000u);
            }
            float ax[8], ay[8];
#pragma unroll
            for (int ii = 0; ii < 8; ii++) { ax[ii] = 0.0f; ay[ii] = 0.0f; }
#pragma unroll
            for (int k = 0; k < 17; k++) {
#pragma unroll
                for (int ii = 0; ii < 8; ii++) {
                    const float a = awT2[(k * 64 + i0 + ii) * 2];
                    ax[ii] += a * xwx[ii + k];
                    ay[ii] += a * xwy[ii + k];
                }
            }
#pragma unroll
            for (int ii = 0; ii < 8; ii++) {
                const float vx = ax[ii], vy = ay[ii];
                const float h0 = __bfloat162float(__float2bfloat16(vx));
                const float h1 = __bfloat162float(__float2bfloat16(vy));
                const int u32i = (mrow + i0 + ii) * 68 + 32 + dp;
                Ah32[u32i] = pack_bf16x2(vx, vy);
                Al32[u32i] = pack_bf16x2(vx - h0, vy - h1);
            }
        }
    }
    __syncthreads();

    // ---- mma.sync GEMM: D[128x64] = Ah*B^T(h) + Ah*B^T(l) + Al*B^T(h) ----
    // 8 warps = 4 m-tiles (32 rows) x 2 n-halves (32 cols)
    {
        const int mt = wid & 3, nh = wid >> 2;
        const int m0 = mt * 32;
        const unsigned rA = (unsigned)(m0 + (lid & 7) + ((lid >> 3) & 1) * 8);
        const unsigned cA = (unsigned)((lid >> 4) * 8);
        unsigned aAddr = sbase + OFF_AH + (rA * 136 + cA) * 2;
        const unsigned rBp = (unsigned)(nh * 32 + (lid >> 4) * 8 + (lid & 7));
        const unsigned cBp = (unsigned)(((lid >> 3) & 1) * 8);
        unsigned bAddr = sbase + OFF_BH + (rBp * 136 + cBp) * 2;

        float acc[2][4][4];
#pragma unroll
        for (int mi = 0; mi < 2; mi++)
#pragma unroll
            for (int nt = 0; nt < 4; nt++)
#pragma unroll
                for (int c = 0; c < 4; c++) acc[mi][nt][c] = 0.0f;

#pragma unroll 1
        for (int ks = 0; ks < 8; ks++) {
            unsigned aH[8], aL[8], bH[8], bL[8];
            ldm4(aH, aAddr);
            ldm4(aH + 4, aAddr + 4352u);                        // +16 rows
            ldm4(aL, aAddr + (OFF_AL - OFF_AH));
            ldm4(aL + 4, aAddr + (OFF_AL - OFF_AH) + 4352u);
            ldm4(bH, bAddr);
            ldm4(bH + 4, bAddr + 4352u);                        // +16 cols
            ldm4(bL, bAddr + (OFF_BL - OFF_BH));
            ldm4(bL + 4, bAddr + (OFF_BL - OFF_BH) + 4352u);
#pragma unroll
            for (int mi = 0; mi < 2; mi++)
#pragma unroll
                for (int nt = 0; nt < 4; nt++) {
                    mma_bf16(acc[mi][nt], aH + 4 * mi, bH + nt * 2);
                    mma_bf16(acc[mi][nt], aH + 4 * mi, bL + nt * 2);
                    mma_bf16(acc[mi][nt], aL + 4 * mi, bH + nt * 2);
                }
            aAddr += 32;
            bAddr += 32;
        }

        // in-register epilogue: relu(bias + acc) over the warp's 32 rows, shfl-reduce
        const int pa = m0 >> 6;            // patch
        const int q  = (m0 >> 5) & 1;      // row-half within patch
        const int cp = (lid & 3) * 2;
#pragma unroll
        for (int nt = 0; nt < 4; nt++) {
            const int o = nh * 32 + nt * 8 + cp;
            const float bb0 = b2s[o], bb1 = b2s[o + 1];
            float p0 = 0.0f, p1 = 0.0f;
#pragma unroll
            for (int mi = 0; mi < 2; mi++) {
                p0 += fmaxf(acc[mi][nt][0] + bb0, 0.0f) + fmaxf(acc[mi][nt][2] + bb0, 0.0f);
                p1 += fmaxf(acc[mi][nt][1] + bb1, 0.0f) + fmaxf(acc[mi][nt][3] + bb1, 0.0f);
            }
            p0 += __shfl_xor_sync(0xffffffffu, p0, 4);
            p1 += __shfl_xor_sync(0xffffffffu, p1, 4);
            p0 += __shfl_xor_sync(0xffffffffu, p0, 8);
            p1 += __shfl_xor_sync(0xffffffffu, p1, 8);
            p0 += __shfl_xor_sync(0xffffffffu, p0, 16);
            p1 += __shfl_xor_sync(0xffffffffu, p1, 16);
            if (lid < 4) {
                part[pa * 128 + q * 64 + o]     = p0;
                part[pa * 128 + q * 64 + o + 1] = p1;
            }
        }
    }
    __syncthreads();
    if (tid < 128) {
        const int pa = tid >> 6, o = tid & 63;
        g_feats[(gp0 + pa) * 64 + o] = part[pa * 128 + o] + part[pa * 128 + 64 + o];
    }
}

// ---------------- xg0 = feats @ Wih0^T + bias : [31744 x 512], K=64 ----------------
__global__ __launch_bounds__(256) void xg0_kernel() {
    __shared__ float As[64 * 64];
    __shared__ float Bs[64 * 64];
    __shared__ float bsm[64];
    const int m0 = blockIdx.x * 64;
    const int n0 = blockIdx.y * 64;
    const int tid = threadIdx.x;
    for (int idx = tid; idx < 1024; idx += 256)
        ((float4*)As)[idx] = *(const float4*)(g_feats + (m0 + (idx >> 4)) * 64 + (idx & 15) * 4);
    for (int idx = tid; idx < 1024; idx += 256)
        ((float4*)Bs)[idx] = *(const float4*)(g_Wih0t + (idx >> 4) * 512 + n0 + (idx & 15) * 4);
    if (tid < 64) bsm[tid] = g_b0c[n0 + tid];
    __syncthreads();
    const int mi0 = (tid >> 4) * 4;
    const int ni0 = (tid & 15) * 4;
    ull acc[4][2];
#pragma unroll
    for (int ii = 0; ii < 4; ii++) { acc[ii][0] = 0ull; acc[ii][1] = 0ull; }
#pragma unroll 2
    for (int k = 0; k < 64; k += 4) {
        ulonglong2 bv[4];
#pragma unroll
        for (int kk = 0; kk < 4; kk++) bv[kk] = *(const ulonglong2*)(Bs + (k + kk) * 64 + ni0);
#pragma unroll
        for (int ii = 0; ii < 4; ii++) {
            const float4 a = *(const float4*)(As + (mi0 + ii) * 64 + k);
            ull p;
            asm("mov.b64 %0, {%1,%1};" : "=l"(p) : "f"(a.x));
            ffma2(acc[ii][0], p, bv[0].x); ffma2(acc[ii][1], p, bv[0].y);
            asm("mov.b64 %0, {%1,%1};" : "=l"(p) : "f"(a.y));
            ffma2(acc[ii][0], p, bv[1].x); ffma2(acc[ii][1], p, bv[1].y);
            asm("mov.b64 %0, {%1,%1};" : "=l"(p) : "f"(a.z));
            ffma2(acc[ii][0], p, bv[2].x); ffma2(acc[ii][1], p, bv[2].y);
            asm("mov.b64 %0, {%1,%1};" : "=l"(p) : "f"(a.w));
            ffma2(acc[ii][0], p, bv[3].x); ffma2(acc[ii][1], p, bv[3].y);
        }
    }
#pragma unroll
    for (int ii = 0; ii < 4; ii++) {
        float2 v01 = unpack2(acc[ii][0]);
        float2 v23 = unpack2(acc[ii][1]);
        float* dst = g_xg0 + (m0 + mi0 + ii) * 512 + n0 + ni0;
        dst[0] = v01.x + bsm[ni0 + 0];
        dst[1] = v01.y + bsm[ni0 + 1];
        dst[2] = v23.x + bsm[ni0 + 2];
        dst[3] = v23.y + bsm[ni0 + 3];
    }
}

// ---------------- pipelined LSTM step (packed weights, pitch 260) ----------------
#define LSTM_SMEM_FLOATS 24832
__global__ __launch_bounds__(256) void lstm_step_kernel(int t) {
    extern __shared__ float sm[];
    const int tid = threadIdx.x;
    const int jj = tid & 31;
    const int bg = tid >> 5;

    if (blockIdx.x < 64) {
        if (t > 30) return;
        const int b0 = (blockIdx.x >> 2) * 64;
        const int j0 = (blockIdx.x & 3) * 32;
        float* Wp = sm;                     // 64*260
        float* hs = sm + 16640;             // [64][128]
        const float* __restrict__ hprev = g_H0[(t + 1) & 1];
        for (int idx = tid; idx < 2048; idx += 256)
            ((float4*)hs)[idx] = *(const float4*)(hprev + b0 * 128 + idx * 4);
        const float4* wsrc = (const float4*)(g_Wp0 + (blockIdx.x & 3) * 16640);
        for (int idx = tid; idx < 4160; idx += 256)
            ((float4*)Wp)[idx] = wsrc[idx];
        __syncthreads();
        ull acc[8][4];
#pragma unroll
        for (int i = 0; i < 8; i++)
#pragma unroll
            for (int q = 0; q < 4; q++) acc[i][q] = 0ull;
#pragma unroll 2
        for (int kp = 0; kp < 64; kp++) {
            const float* wrow = Wp + kp * 260 + jj * 2;
            const ull w0 = *(const ull*)(wrow);
            const ull w1v = *(const ull*)(wrow + 64);
            const ull w2 = *(const ull*)(wrow + 128);
            const ull w3 = *(const ull*)(wrow + 192);
#pragma unroll
            for (int i = 0; i < 8; i++) {
                const ull h = *(const ull*)(hs + (bg * 8 + i) * 128 + kp * 2);
                ffma2(acc[i][0], h, w0);
                ffma2(acc[i][1], h, w1v);
                ffma2(acc[i][2], h, w2);
                ffma2(acc[i][3], h, w3);
            }
        }
        const int j = j0 + jj;
#pragma unroll
        for (int i = 0; i < 8; i++) {
            int b = b0 + bg * 8 + i;
            const float* xg = g_xg0 + (b * NP + t) * 512;
            float2 s0 = unpack2(acc[i][0]);
            float2 s1 = unpack2(acc[i][1]);
            float2 s2 = unpack2(acc[i][2]);
            float2 s3 = unpack2(acc[i][3]);
            float gi = s0.x + s0.y + xg[j];
            float gf = s1.x + s1.y + xg[128 + j];
            float gg = s2.x + s2.y + xg[256 + j];
            float go = s3.x + s3.y + xg[384 + j];
            float c = g_C0[b * 128 + j];
            c = sigm(gf) * c + sigm(gi) * tanhf(gg);
            float h = sigm(go) * tanhf(c);
            g_C0[b * 128 + j] = c;
            g_H0[t & 1][b * 128 + j] = h;
        }
    } else {
        const int s = t - 1;
        if (s < 0) return;
        const int blk = blockIdx.x - 64;
        const int b0 = (blk >> 2) * 32;
        const int j0 = (blk & 3) * 32;
        float* Wp  = sm;
        float* h0s = sm + 16640;            // [32][128]
        float* h1s = h0s + 4096;            // [32][128]
        const float* __restrict__ h0in = g_H0[s & 1];
        const float* __restrict__ h1in = g_H1[(s & 1) ^ 1];
        for (int idx = tid; idx < 1024; idx += 256) {
            ((float4*)h0s)[idx] = *(const float4*)(h0in + b0 * 128 + idx * 4);
            ((float4*)h1s)[idx] = *(const float4*)(h1in + b0 * 128 + idx * 4);
        }
        const float4* wsrc1 = (const float4*)(g_Wp1i + (blk & 3) * 16640);
        for (int idx = tid; idx < 4160; idx += 256)
            ((float4*)Wp)[idx] = wsrc1[idx];
        __syncthreads();
        ull acc[4][4];
#pragma unroll
        for (int i = 0; i < 4; i++)
#pragma unroll
            for (int q = 0; q < 4; q++) acc[i][q] = 0ull;
#pragma unroll 2
        for (int kp = 0; kp < 64; kp++) {
            const float* wrow = Wp + kp * 260 + jj * 2;
            const ull w0 = *(const ull*)(wrow);
            const ull w1v = *(const ull*)(wrow + 64);
            const ull w2 = *(const ull*)(wrow + 128);
            const ull w3 = *(const ull*)(wrow + 192);
#pragma unroll
            for (int i = 0; i < 4; i++) {
                const ull h = *(const ull*)(h0s + (bg * 4 + i) * 128 + kp * 2);
                ffma2(acc[i][0], h, w0);
                ffma2(acc[i][1], h, w1v);
                ffma2(acc[i][2], h, w2);
                ffma2(acc[i][3], h, w3);
            }
        }
        __syncthreads();
        const float4* wsrc2 = (const float4*)(g_Wp1h + (blk & 3) * 16640);
        for (int idx = tid; idx < 4160; idx += 256)
            ((float4*)Wp)[idx] = wsrc2[idx];
        __syncthreads();
#pragma unroll 2
        for (int kp = 0; kp < 64; kp++) {
            const float* wrow = Wp + kp * 260 + jj * 2;
            const ull w0 = *(const ull*)(wrow);
            const ull w1v = *(const ull*)(wrow + 64);
            const ull w2 = *(const ull*)(wrow + 128);
            const ull w3 = *(const ull*)(wrow + 192);
#pragma unroll
            for (int i = 0; i < 4; i++) {
                const ull h = *(const ull*)(h1s + (bg * 4 + i) * 128 + kp * 2);
                ffma2(acc[i][0], h, w0);
                ffma2(acc[i][1], h, w1v);
                ffma2(acc[i][2], h, w2);
                ffma2(acc[i][3], h, w3);
            }
        }
        const int j = j0 + jj;
#pragma unroll
        for (int i = 0; i < 4; i++) {
            int b = b0 + bg * 4 + i;
            float2 s0 = unpack2(acc[i][0]);
            float2 s1 = unpack2(acc[i][1]);
            float2 s2 = unpack2(acc[i][2]);
            float2 s3 = unpack2(acc[i][3]);
            float gi = s0.x + s0.y + g_b1l[j];
            float gf = s1.x + s1.y + g_b1l[128 + j];
            float gg = s2.x + s2.y + g_b1l[256 + j];
            float go = s3.x + s3.y + g_b1l[384 + j];
            float c = g_C1[b * 128 + j];
            c = sigm(gf) * c + sigm(gi) * tanhf(gg);
            float h = sigm(go) * tanhf(c);
            g_C1[b * 128 + j] = c;
            g_H1[s & 1][b * 128 + j] = h;
        }
    }
}

// ---------------- classifier ----------------
__global__ __launch_bounds__(256) void fc1_kernel(const float* __restrict__ bc1) {
    __shared__ float w[128 * 64];
    __shared__ float hsm[4 * 128];
    __shared__ float bsm[64];
    const int tid = threadIdx.x;
    const int b0 = blockIdx.x * 4;
    for (int idx = tid; idx < 8192; idx += 256) w[idx] = g_Wc1t[idx];
    if (tid < 64) bsm[tid] = bc1[tid];
    for (int idx = tid; idx < 512; idx += 256) hsm[idx] = g_H1[0][b0 * 128 + idx];
    __syncthreads();
    const int o = tid & 63, bb = tid >> 6;
    float s = bsm[o];
#pragma unroll 8
    for (int k = 0; k < 128; k++) s += hsm[bb * 128 + k] * w[k * 64 + o];
    g_hid[(b0 + bb) * 64 + o] = fmaxf(s, 0.0f);
}

__global__ __launch_bounds__(256) void fc2_kernel(const float* __restrict__ Wc2,
                                                  const float* __restrict__ bc2,
                                                  float* __restrict__ out) {
    __shared__ float w[11 * 64];
    __shared__ float bsm[11];
    __shared__ float hs[16 * 64];
    const int tid = threadIdx.x;
    const int b0 = blockIdx.x * 16;
    for (int idx = tid; idx < 704; idx += 256) w[idx] = Wc2[idx];
    if (tid < 11) bsm[tid] = bc2[tid];
    for (int idx = tid; idx < 1024; idx += 256) hs[idx] = g_hid[b0 * 64 + idx];
    __syncthreads();
    if (tid < 176) {
        int bb = tid / 11, c = tid - bb * 11;
        float s = bsm[c];
#pragma unroll 8
        for (int k = 0; k < 64; k++) s += hs[bb * 64 + k] * w[c * 64 + k];
        out[(b0 + bb) * 11 + c] = s;
    }
}

// ---------------- launch ----------------
extern "C" void kernel_launch(void* const* d_in, const int* in_sizes, int n_in,
                              void* d_out, int out_size) {
    const float* I    = (const float*)d_in[0];
    const float* Q    = (const float*)d_in[1];
    const float* E    = (const float*)d_in[2];
    const float* Wn1  = (const float*)d_in[3];
    const float* bn1  = (const float*)d_in[4];
    const float* Ws1  = (const float*)d_in[5];
    const float* bs1  = (const float*)d_in[6];
    const float* Wn2  = (const float*)d_in[7];
    const float* bn2  = (const float*)d_in[8];
    const float* Ws2  = (const float*)d_in[9];
    const float* bs2  = (const float*)d_in[10];
    const float* Wih0 = (const float*)d_in[11];
    const float* Whh0 = (const float*)d_in[12];
    const float* bih0 = (const float*)d_in[13];
    const float* bhh0 = (const float*)d_in[14];
    const float* Wih1 = (const float*)d_in[15];
    const float* Whh1 = (const float*)d_in[16];
    const float* bih1 = (const float*)d_in[17];
    const float* bhh1 = (const float*)d_in[18];
    const float* Wc1  = (const float*)d_in[19];
    const float* bc1  = (const float*)d_in[20];
    const float* Wc2  = (const float*)d_in[21];
    const float* bc2  = (const float*)d_in[22];
    float* out = (float*)d_out;

    const size_t lstm_smem = LSTM_SMEM_FLOATS * sizeof(float);  // 99328 B
    cudaFuncSetAttribute(gnn_kernel, cudaFuncAttributeMaxDynamicSharedMemorySize, GNN_SMEM_BYTES);
    cudaFuncSetAttribute(lstm_step_kernel, cudaFuncAttributeMaxDynamicSharedMemorySize, (int)lstm_smem);

    // launch order chosen so gnn_kernel lands in the ncu capture slot (4th launch)
    prep_kernel<<<1, 256>>>(E, Wn1, bn1, Ws1, bs1, Wn2, bn2, Ws2, bs2,
                            bih0, bhh0, bih1, bhh1);
    prep_big_kernel<<<256, 256>>>(Wih0, Wc1, Whh0, Wih1, Whh1);
    zero_kernel<<<512, 256>>>();
    gnn_kernel<<<(NBATCH * NP) / 2, 256, GNN_SMEM_BYTES>>>(I, Q);
    xg0_kernel<<<dim3((NBATCH * NP) / 64, 8), 256>>>();
    for (int t = 0; t < 32; t++)
        lstm_step_kernel<<<192, 256, lstm_smem>>>(t);
    fc1_kernel<<<NBATCH / 4, 256>>>(bc1);
    fc2_kernel<<<NBATCH / 16, 256>>>(Wc2, bc2, out);
    (void)in_sizes; (void)n_in; (void)out_size;
}